// round 7
// baseline (speedup 1.0000x reference)
#include <cuda_runtime.h>
#include <cuda_bf16.h>
#include <cstdint>

// Problem constants
#define BB   8
#define ND   12288
#define NU   49152
#define CI   64
#define CO   32
#define SP   9
#define NNZE 147456
#define KTOT (SP * CI)   // 576

// ---------------------------------------------------------------------------
// Device scratch
// ---------------------------------------------------------------------------
__device__ int g_cnt[NU];
__device__ int g_off[NU + 1];
__device__ int g_wp[NU];
__device__ int g_eid[NNZE];
// pooled, split bf16 planes: [b][row][64ch], each row 128B
__device__ __align__(256) unsigned short g_ph[(size_t)BB * NU * CI];
__device__ __align__(256) unsigned short g_pl[(size_t)BB * NU * CI];
// weight, split bf16, [s][n=32][k=64] with 16B-unit XOR swizzle, ldmatrix-ready
__device__ __align__(256) unsigned short g_wh[SP * CO * CI];
__device__ __align__(256) unsigned short g_wl[SP * CO * CI];

// ---------------------------------------------------------------------------
// Launch 0: zero counts + weight split/swizzle prepack
// ---------------------------------------------------------------------------
__global__ void init_misc(const float* __restrict__ weight) {
    int i = blockIdx.x * blockDim.x + threadIdx.x;
    if (i < NU) g_cnt[i] = 0;
    if (i < SP * CO * CI) {
        int k = i & 63;
        int n = (i >> 6) & 31;
        int s = i >> 11;
        float v = __ldg(weight + n * KTOT + s * CI + k);
        __nv_bfloat16 hi = __float2bfloat16(v);
        __nv_bfloat16 lo = __float2bfloat16(v - __bfloat162float(hi));
        int unit = k >> 3;
        int within = (k * 2) & 15;
        int byte = s * 4096 + n * 128 + ((unit ^ (n & 7)) << 4) + within;
        g_wh[byte >> 1] = __bfloat16_as_ushort(hi);
        g_wl[byte >> 1] = __bfloat16_as_ushort(lo);
    }
}

// ---------------------------------------------------------------------------
// Launch 1: histogram of rows
// ---------------------------------------------------------------------------
__global__ void hist_rows(const int* __restrict__ rows) {
    int e = blockIdx.x * blockDim.x + threadIdx.x;
    if (e < NNZE) atomicAdd(&g_cnt[__ldg(rows + e)], 1);
}

// ---------------------------------------------------------------------------
// Launch 2: single-block scan + CSR fill
// ---------------------------------------------------------------------------
__global__ void __launch_bounds__(1024)
scan_fill(const int* __restrict__ rows) {
    __shared__ int warp_sums[32];
    const int t = threadIdx.x, lane = t & 31, w = t >> 5;
    const int base = t * (NU / 1024);

    int local = 0;
#pragma unroll 4
    for (int j = 0; j < NU / 1024; j++) local += g_cnt[base + j];

    int v = local;
#pragma unroll
    for (int d = 1; d < 32; d <<= 1) {
        int n = __shfl_up_sync(0xffffffffu, v, d);
        if (lane >= d) v += n;
    }
    if (lane == 31) warp_sums[w] = v;
    __syncthreads();
    if (w == 0) {
        int s = warp_sums[lane];
#pragma unroll
        for (int d = 1; d < 32; d <<= 1) {
            int n = __shfl_up_sync(0xffffffffu, s, d);
            if (lane >= d) s += n;
        }
        warp_sums[lane] = s;
    }
    __syncthreads();

    int run = (v - local) + (w > 0 ? warp_sums[w - 1] : 0);
#pragma unroll 4
    for (int j = 0; j < NU / 1024; j++) {
        int c = g_cnt[base + j];
        g_off[base + j] = run;
        g_wp[base + j]  = run;
        run += c;
    }
    if (t == 1023) g_off[NU] = run;
    __syncthreads();

    for (int e = t; e < NNZE; e += 1024) {
        int p = atomicAdd(&g_wp[__ldg(rows + e)], 1);
        g_eid[p] = e;
    }
}

// ---------------------------------------------------------------------------
// Launch 3: gather-pool -> bf16 hi/lo planes.
// ---------------------------------------------------------------------------
__global__ void __launch_bounds__(256)
gather_pool(const float* __restrict__ x,
            const int*   __restrict__ cols,
            const float* __restrict__ vals) {
    int gt  = blockIdx.x * blockDim.x + threadIdx.x;
    int row = gt >> 4;
    int c4  = gt & 15;
    if (row >= NU) return;

    int s = g_off[row];
    int e = g_off[row + 1];

    float4 acc[BB];
#pragma unroll
    for (int b = 0; b < BB; b++) acc[b] = make_float4(0.f, 0.f, 0.f, 0.f);

    for (int i = s; i < e; i++) {
        int   eid = g_eid[i];
        int   col = __ldg(cols + eid);
        float v   = __ldg(vals + eid);
        const float4* xp = reinterpret_cast<const float4*>(x) + (size_t)col * 16 + c4;
#pragma unroll
        for (int b = 0; b < BB; b++) {
            float4 xv = __ldg(xp + (size_t)b * (ND * 16));
            acc[b].x += v * xv.x; acc[b].y += v * xv.y;
            acc[b].z += v * xv.z; acc[b].w += v * xv.w;
        }
    }

#pragma unroll
    for (int b = 0; b < BB; b++) {
        float f[4] = {acc[b].x, acc[b].y, acc[b].z, acc[b].w};
        ushort4 h, l;
        unsigned short* hp = &h.x;
        unsigned short* lp = &l.x;
#pragma unroll
        for (int j = 0; j < 4; j++) {
            __nv_bfloat16 hb = __float2bfloat16(f[j]);
            __nv_bfloat16 lb = __float2bfloat16(f[j] - __bfloat162float(hb));
            hp[j] = __bfloat16_as_ushort(hb);
            lp[j] = __bfloat16_as_ushort(lb);
        }
        size_t off = ((size_t)b * NU + row) * CI + c4 * 4;
        *reinterpret_cast<ushort4*>(g_ph + off) = h;
        *reinterpret_cast<ushort4*>(g_pl + off) = l;
    }
}

// ---------------------------------------------------------------------------
// Launch 4: fused spiral gather + mma.sync bf16-split GEMM + bias + relu.
// A gathered with cp.async.bulk (128B per row-plane, mbarrier complete_tx),
// double-buffered; A rows at 144B stride -> ldmatrix conflict-free w/o XOR.
// W resident (XOR-swizzled); 3-term bf16 split accumulation.
// ---------------------------------------------------------------------------
#define TILE_R  128
#define APLANE  (TILE_R * 144)           // 18432 B
#define ABUF    (2 * APLANE)             // 36864 B per buffer
#define SM_MBAR 0                        // 2 mbarriers (16 B)
#define SM_W    128                      // 73728 B (hi | lo)
#define SM_SG   (SM_W + SP * 4096 * 2)   // 73856: spiral indices (4608 B)
#define SM_A    (SM_SG + TILE_R * SP * 4)    // 78464 (128-aligned)
#define SM_TOT  (SM_A + 2 * ABUF)            // 152192 B

__device__ __forceinline__ uint32_t smem_u32(const void* p) {
    uint32_t a;
    asm("{ .reg .u64 t; cvta.to.shared.u64 t, %1; cvt.u32.u64 %0, t; }" : "=r"(a) : "l"(p));
    return a;
}
__device__ __forceinline__ void cp16(uint32_t dst, const void* src) {
    asm volatile("cp.async.cg.shared.global [%0], [%1], 16;" :: "r"(dst), "l"(src));
}
#define CP_COMMIT() asm volatile("cp.async.commit_group;" ::: "memory")
#define CP_WAIT(n)  asm volatile("cp.async.wait_group %0;" :: "n"(n) : "memory")

__device__ __forceinline__ void mbar_init(uint32_t m, uint32_t cnt) {
    asm volatile("mbarrier.init.shared.b64 [%0], %1;" :: "r"(m), "r"(cnt) : "memory");
}
__device__ __forceinline__ void mbar_expect_tx(uint32_t m, uint32_t bytes) {
    asm volatile("mbarrier.arrive.expect_tx.shared.b64 _, [%0], %1;"
                 :: "r"(m), "r"(bytes) : "memory");
}
__device__ __forceinline__ void mbar_wait(uint32_t m, uint32_t parity) {
    asm volatile(
        "{\n\t.reg .pred P;\n"
        "W_%=:\n\t"
        "mbarrier.try_wait.parity.shared::cta.b64 P, [%0], %1;\n\t"
        "@!P bra W_%=;\n\t}"
        :: "r"(m), "r"(parity) : "memory");
}
__device__ __forceinline__ void bulk_g2s(uint32_t dst, const void* src,
                                         uint32_t bytes, uint32_t mbar) {
    asm volatile(
        "cp.async.bulk.shared::cluster.global.mbarrier::complete_tx::bytes "
        "[%0], [%1], %2, [%3];"
        :: "r"(dst), "l"(src), "r"(bytes), "r"(mbar) : "memory");
}

__device__ __forceinline__ void ldsm4(uint32_t addr, uint32_t& r0, uint32_t& r1,
                                      uint32_t& r2, uint32_t& r3) {
    asm volatile("ldmatrix.sync.aligned.m8n8.x4.shared.b16 {%0,%1,%2,%3}, [%4];"
                 : "=r"(r0), "=r"(r1), "=r"(r2), "=r"(r3) : "r"(addr));
}
__device__ __forceinline__ void mma_bf16(float* c, uint32_t a0, uint32_t a1,
                                         uint32_t a2, uint32_t a3,
                                         uint32_t b0, uint32_t b1) {
    asm volatile(
        "mma.sync.aligned.m16n8k16.row.col.f32.bf16.bf16.f32 "
        "{%0,%1,%2,%3}, {%4,%5,%6,%7}, {%8,%9}, {%0,%1,%2,%3};"
        : "+f"(c[0]), "+f"(c[1]), "+f"(c[2]), "+f"(c[3])
        : "r"(a0), "r"(a1), "r"(a2), "r"(a3), "r"(b0), "r"(b1));
}

__global__ void __launch_bounds__(256, 1)
spiral_mma(const int*   __restrict__ sidx,
           const float* __restrict__ bias,
           float*       __restrict__ out) {
    extern __shared__ char smraw[];
    uint32_t smb = smem_u32(smraw);

    const int tid  = threadIdx.x;
    const int wid  = tid >> 5;
    const int lane = tid & 31;
    const int b    = blockIdx.y;
    const int n0   = blockIdx.x * TILE_R;

    const char* phB = reinterpret_cast<const char*>(g_ph) + (size_t)b * NU * 128;
    const char* plB = reinterpret_cast<const char*>(g_pl) + (size_t)b * NU * 128;
    int* Sg = reinterpret_cast<int*>(smraw + SM_SG);

    // mbarrier init: one per A buffer, 256 arrivals per phase
    if (tid == 0) {
        mbar_init(smb + SM_MBAR + 0, 256);
        mbar_init(smb + SM_MBAR + 8, 256);
    }

    // Stage W hi/lo (pre-swizzled) via cp.async (single group)
    {
        const char* wh = reinterpret_cast<const char*>(g_wh);
        const char* wl = reinterpret_cast<const char*>(g_wl);
        for (int i = tid; i < SP * 4096 / 16; i += 256) {
            cp16(smb + SM_W + i * 16, wh + i * 16);
            cp16(smb + SM_W + SP * 4096 + i * 16, wl + i * 16);
        }
        CP_COMMIT();
    }
    for (int i = tid; i < TILE_R * SP; i += 256)
        Sg[i] = __ldg(sidx + (size_t)n0 * SP + i);
    __syncthreads();   // Sg + mbarrier init visible

    // Per-thread gather slot: one 128B bulk copy per (row, plane)
    const int grow   = tid & 127;
    const int gplane = tid >> 7;
    const char* gsrcB = gplane ? plB : phB;

    auto gather = [&](int s) {
        int buf = s & 1;
        uint32_t mbar = smb + SM_MBAR + buf * 8;
        uint32_t dst  = smb + SM_A + buf * ABUF + gplane * APLANE + grow * 144;
        int idx = Sg[grow * SP + s];
        mbar_expect_tx(mbar, 128);
        bulk_g2s(dst, gsrcB + (size_t)idx * 128, 128, mbar);
    };

    gather(0);
    gather(1);

    CP_WAIT(0);        // W landed
    __syncthreads();

    float acc[4][4];
#pragma unroll
    for (int i = 0; i < 4; i++)
#pragma unroll
        for (int j = 0; j < 4; j++) acc[i][j] = 0.f;

    // ldmatrix geometry
    const int m8   = lane >> 3;
    const int t8   = lane & 7;
    const int arow = wid * 16 + (m8 & 1) * 8 + t8;
    const int mk   = m8 >> 1;

#pragma unroll 1
    for (int s = 0; s < SP; s++) {
        mbar_wait(smb + SM_MBAR + (s & 1) * 8, (s >> 1) & 1);

        uint32_t abase = smb + SM_A + (s & 1) * ABUF;
        uint32_t wbase = smb + SM_W + s * 4096;

#pragma unroll
        for (int ks = 0; ks < 4; ks++) {
            int unit = 2 * ks + mk;
            uint32_t aaddr = abase + arow * 144 + unit * 16;
            uint32_t ah[4], al[4];
            ldsm4(aaddr,          ah[0], ah[1], ah[2], ah[3]);
            ldsm4(aaddr + APLANE, al[0], al[1], al[2], al[3]);
            uint32_t bh0[4], bh1[4], bl0[4], bl1[4];
#pragma unroll
            for (int nb = 0; nb < 2; nb++) {
                int nrow = nb * 16 + (m8 & 1) * 8 + t8;
                uint32_t baddr = wbase + nrow * 128 + ((unit ^ (nrow & 7)) << 4);
                uint32_t* bh = nb ? bh1 : bh0;
                uint32_t* bl = nb ? bl1 : bl0;
                ldsm4(baddr,             bh[0], bh[1], bh[2], bh[3]);
                ldsm4(baddr + SP * 4096, bl[0], bl[1], bl[2], bl[3]);
            }
            mma_bf16(acc[0], ah[0], ah[1], ah[2], ah[3], bh0[0], bh0[2]);
            mma_bf16(acc[1], ah[0], ah[1], ah[2], ah[3], bh0[1], bh0[3]);
            mma_bf16(acc[2], ah[0], ah[1], ah[2], ah[3], bh1[0], bh1[2]);
            mma_bf16(acc[3], ah[0], ah[1], ah[2], ah[3], bh1[1], bh1[3]);
            mma_bf16(acc[0], al[0], al[1], al[2], al[3], bh0[0], bh0[2]);
            mma_bf16(acc[1], al[0], al[1], al[2], al[3], bh0[1], bh0[3]);
            mma_bf16(acc[2], al[0], al[1], al[2], al[3], bh1[0], bh1[2]);
            mma_bf16(acc[3], al[0], al[1], al[2], al[3], bh1[1], bh1[3]);
            mma_bf16(acc[0], ah[0], ah[1], ah[2], ah[3], bl0[0], bl0[2]);
            mma_bf16(acc[1], ah[0], ah[1], ah[2], ah[3], bl0[1], bl0[3]);
            mma_bf16(acc[2], ah[0], ah[1], ah[2], ah[3], bl1[0], bl1[2]);
            mma_bf16(acc[3], ah[0], ah[1], ah[2], ah[3], bl1[1], bl1[3]);
        }

        __syncthreads();   // all warps done reading buf (s&1)
        if (s + 2 < SP) gather(s + 2);
    }

    // Epilogue: bias + relu, float2 stores
    const int r0  = wid * 16 + (lane >> 2);
    const int col = (lane & 3) * 2;
    float* po0 = out + ((size_t)b * NU + n0 + r0) * CO;
    float* po1 = po0 + 8 * CO;
#pragma unroll
    for (int nt = 0; nt < 4; nt++) {
        int o = nt * 8 + col;
        float b0 = __ldg(bias + o), b1 = __ldg(bias + o + 1);
        float2 v0 = make_float2(fmaxf(acc[nt][0] + b0, 0.f), fmaxf(acc[nt][1] + b1, 0.f));
        float2 v1 = make_float2(fmaxf(acc[nt][2] + b0, 0.f), fmaxf(acc[nt][3] + b1, 0.f));
        *reinterpret_cast<float2*>(po0 + o) = v0;
        *reinterpret_cast<float2*>(po1 + o) = v1;
    }
}

// ---------------------------------------------------------------------------
// Launch (5 kernels)
// ---------------------------------------------------------------------------
extern "C" void kernel_launch(void* const* d_in, const int* in_sizes, int n_in,
                              void* d_out, int out_size) {
    const float* x        = (const float*)d_in[0];
    const int*   up_rows  = (const int*)  d_in[1];
    const int*   up_cols  = (const int*)  d_in[2];
    const float* up_vals  = (const float*)d_in[3];
    const int*   sidx     = (const int*)  d_in[4];
    const float* weight   = (const float*)d_in[5];
    const float* bias     = (const float*)d_in[6];
    float*       out      = (float*)d_out;

    init_misc<<<(NU + 255) / 256, 256>>>(weight);
    hist_rows<<<(NNZE + 255) / 256, 256>>>(up_rows);
    scan_fill<<<1, 1024>>>(up_rows);
    gather_pool<<<(NU * 16) / 256, 256>>>(x, up_cols, up_vals);

    cudaFuncSetAttribute(spiral_mma,
                         cudaFuncAttributeMaxDynamicSharedMemorySize, SM_TOT);
    dim3 grid(NU / TILE_R, BB);
    spiral_mma<<<grid, 256, SM_TOT>>>(sidx, bias, out);
}

// round 8
// speedup vs baseline: 1.2067x; 1.2067x over previous
#include <cuda_runtime.h>
#include <cuda_bf16.h>
#include <cstdint>

// Problem constants
#define BB   8
#define ND   12288
#define NU   49152
#define CI   64
#define CO   32
#define SP   9
#define NNZE 147456
#define KTOT (SP * CI)   // 576

// ---------------------------------------------------------------------------
// Device scratch (statics are zero-initialized; g_cnt re-zeroed by spiral_mma
// each call so hist_rows can run first next call)
// ---------------------------------------------------------------------------
__device__ int g_cnt[NU];
__device__ int g_off[NU + 1];
__device__ int g_wp[NU];
__device__ int g_eid[NNZE];
// pooled: per row a 2KB chunk: [hi: b0..b7 x 128B | lo: b0..b7 x 128B],
// within (plane,b): 16B unit u stored at offset ((u ^ b) << 4)  (bank-spread)
__device__ __align__(256) unsigned char g_pool[(size_t)NU * 2048];
// weight, split bf16, [s][n=32][k=64] with 16B-unit XOR swizzle, ldmatrix-ready
__device__ __align__(256) unsigned short g_wh[SP * CO * CI];
__device__ __align__(256) unsigned short g_wl[SP * CO * CI];

// ---------------------------------------------------------------------------
// Launch 0: histogram of rows (g_cnt is zero from static init / prev call)
// ---------------------------------------------------------------------------
__global__ void hist_rows(const int* __restrict__ rows) {
    int e = blockIdx.x * blockDim.x + threadIdx.x;
    if (e < NNZE) atomicAdd(&g_cnt[__ldg(rows + e)], 1);
}

// ---------------------------------------------------------------------------
// Launch 1: single-block scan + CSR fill + weight split/swizzle prepack
// ---------------------------------------------------------------------------
__global__ void __launch_bounds__(1024)
scan_fill(const int* __restrict__ rows, const float* __restrict__ weight) {
    __shared__ int warp_sums[32];
    const int t = threadIdx.x, lane = t & 31, w = t >> 5;

    // Weight prepack (independent)
    for (int i = t; i < SP * CO * CI; i += 1024) {
        int k = i & 63;
        int n = (i >> 6) & 31;
        int s = i >> 11;
        float v = __ldg(weight + n * KTOT + s * CI + k);
        __nv_bfloat16 hi = __float2bfloat16(v);
        __nv_bfloat16 lo = __float2bfloat16(v - __bfloat162float(hi));
        int unit = k >> 3;
        int within = (k * 2) & 15;
        int byte = s * 4096 + n * 128 + ((unit ^ (n & 7)) << 4) + within;
        g_wh[byte >> 1] = __bfloat16_as_ushort(hi);
        g_wl[byte >> 1] = __bfloat16_as_ushort(lo);
    }

    const int base = t * (NU / 1024);
    int local = 0;
#pragma unroll 4
    for (int j = 0; j < NU / 1024; j++) local += g_cnt[base + j];

    int v = local;
#pragma unroll
    for (int d = 1; d < 32; d <<= 1) {
        int n = __shfl_up_sync(0xffffffffu, v, d);
        if (lane >= d) v += n;
    }
    if (lane == 31) warp_sums[w] = v;
    __syncthreads();
    if (w == 0) {
        int s = warp_sums[lane];
#pragma unroll
        for (int d = 1; d < 32; d <<= 1) {
            int n = __shfl_up_sync(0xffffffffu, s, d);
            if (lane >= d) s += n;
        }
        warp_sums[lane] = s;
    }
    __syncthreads();

    int run = (v - local) + (w > 0 ? warp_sums[w - 1] : 0);
#pragma unroll 4
    for (int j = 0; j < NU / 1024; j++) {
        int c = g_cnt[base + j];
        g_off[base + j] = run;
        g_wp[base + j]  = run;
        run += c;
    }
    if (t == 1023) g_off[NU] = run;
    __syncthreads();

    for (int e = t; e < NNZE; e += 1024) {
        int p = atomicAdd(&g_wp[__ldg(rows + e)], 1);
        g_eid[p] = e;
    }
}

// ---------------------------------------------------------------------------
// Launch 2: gather-pool -> per-row 2KB chunks (hi/lo planes, batch-XOR units)
// thread = (row, c4): channels 4*c4..4*c4+3 (8B half of unit u=c4>>1)
// ---------------------------------------------------------------------------
__global__ void __launch_bounds__(256)
gather_pool(const float* __restrict__ x,
            const int*   __restrict__ cols,
            const float* __restrict__ vals) {
    int gt  = blockIdx.x * blockDim.x + threadIdx.x;
    int row = gt >> 4;
    int c4  = gt & 15;
    if (row >= NU) return;

    int s = g_off[row];
    int e = g_off[row + 1];

    float4 acc[BB];
#pragma unroll
    for (int b = 0; b < BB; b++) acc[b] = make_float4(0.f, 0.f, 0.f, 0.f);

    for (int i = s; i < e; i++) {
        int   eid = g_eid[i];
        int   col = __ldg(cols + eid);
        float v   = __ldg(vals + eid);
        const float4* xp = reinterpret_cast<const float4*>(x) + (size_t)col * 16 + c4;
#pragma unroll
        for (int b = 0; b < BB; b++) {
            float4 xv = __ldg(xp + (size_t)b * (ND * 16));
            acc[b].x += v * xv.x; acc[b].y += v * xv.y;
            acc[b].z += v * xv.z; acc[b].w += v * xv.w;
        }
    }

    const int u = c4 >> 1;          // 16B unit 0..7
    const int h = c4 & 1;           // 8B half within unit
    unsigned char* chunk = g_pool + (size_t)row * 2048;
#pragma unroll
    for (int b = 0; b < BB; b++) {
        float f[4] = {acc[b].x, acc[b].y, acc[b].z, acc[b].w};
        ushort4 hh, ll;
        unsigned short* hp = &hh.x;
        unsigned short* lp = &ll.x;
#pragma unroll
        for (int j = 0; j < 4; j++) {
            __nv_bfloat16 hb = __float2bfloat16(f[j]);
            __nv_bfloat16 lb = __float2bfloat16(f[j] - __bfloat162float(hb));
            hp[j] = __bfloat16_as_ushort(hb);
            lp[j] = __bfloat16_as_ushort(lb);
        }
        int off = b * 128 + ((u ^ b) << 4) + h * 8;
        *reinterpret_cast<ushort4*>(chunk + off)        = hh;   // hi plane
        *reinterpret_cast<ushort4*>(chunk + 1024 + off) = ll;   // lo plane
    }
}

// ---------------------------------------------------------------------------
// Launch 3: fused spiral gather + mma.sync bf16-split GEMM + bias + relu.
// Block = 16 spiral rows x 8 batches = 128 GEMM rows x 32 outs.
// Per stage: 16 bulk copies of 2KB (one per spiral row) into a 3-deep ring.
// Also re-zeros g_cnt for the next call.
// ---------------------------------------------------------------------------
#define ABUF    32768                       // 16 rows * 2KB
#define SM_MBAR 0                           // 3 mbarriers
#define SM_W    128                         // 73728 B (hi | lo)
#define SM_SG   (SM_W + SP * 4096 * 2)      // 73856: 144 spiral indices
#define SM_A    74752                       // 3 x 32KB ring
#define SM_TOT  (SM_A + 3 * ABUF)           // 173056 B

__device__ __forceinline__ uint32_t smem_u32(const void* p) {
    uint32_t a;
    asm("{ .reg .u64 t; cvta.to.shared.u64 t, %1; cvt.u32.u64 %0, t; }" : "=r"(a) : "l"(p));
    return a;
}
__device__ __forceinline__ void cp16(uint32_t dst, const void* src) {
    asm volatile("cp.async.cg.shared.global [%0], [%1], 16;" :: "r"(dst), "l"(src));
}
#define CP_COMMIT() asm volatile("cp.async.commit_group;" ::: "memory")
#define CP_WAIT(n)  asm volatile("cp.async.wait_group %0;" :: "n"(n) : "memory")

__device__ __forceinline__ void mbar_init(uint32_t m, uint32_t cnt) {
    asm volatile("mbarrier.init.shared.b64 [%0], %1;" :: "r"(m), "r"(cnt) : "memory");
}
__device__ __forceinline__ void mbar_expect_tx(uint32_t m, uint32_t bytes) {
    asm volatile("mbarrier.arrive.expect_tx.shared.b64 _, [%0], %1;"
                 :: "r"(m), "r"(bytes) : "memory");
}
__device__ __forceinline__ void mbar_wait(uint32_t m, uint32_t parity) {
    asm volatile(
        "{\n\t.reg .pred P;\n"
        "W_%=:\n\t"
        "mbarrier.try_wait.parity.shared::cta.b64 P, [%0], %1;\n\t"
        "@!P bra W_%=;\n\t}"
        :: "r"(m), "r"(parity) : "memory");
}
__device__ __forceinline__ void bulk_g2s(uint32_t dst, const void* src,
                                         uint32_t bytes, uint32_t mbar) {
    asm volatile(
        "cp.async.bulk.shared::cluster.global.mbarrier::complete_tx::bytes "
        "[%0], [%1], %2, [%3];"
        :: "r"(dst), "l"(src), "r"(bytes), "r"(mbar) : "memory");
}
__device__ __forceinline__ void ldsm4(uint32_t addr, uint32_t& r0, uint32_t& r1,
                                      uint32_t& r2, uint32_t& r3) {
    asm volatile("ldmatrix.sync.aligned.m8n8.x4.shared.b16 {%0,%1,%2,%3}, [%4];"
                 : "=r"(r0), "=r"(r1), "=r"(r2), "=r"(r3) : "r"(addr));
}
__device__ __forceinline__ void mma_bf16(float* c, uint32_t a0, uint32_t a1,
                                         uint32_t a2, uint32_t a3,
                                         uint32_t b0, uint32_t b1) {
    asm volatile(
        "mma.sync.aligned.m16n8k16.row.col.f32.bf16.bf16.f32 "
        "{%0,%1,%2,%3}, {%4,%5,%6,%7}, {%8,%9}, {%0,%1,%2,%3};"
        : "+f"(c[0]), "+f"(c[1]), "+f"(c[2]), "+f"(c[3])
        : "r"(a0), "r"(a1), "r"(a2), "r"(a3), "r"(b0), "r"(b1));
}

__global__ void __launch_bounds__(256, 1)
spiral_mma(const int*   __restrict__ sidx,
           const float* __restrict__ bias,
           float*       __restrict__ out) {
    extern __shared__ char smraw[];
    uint32_t smb = smem_u32(smraw);

    const int tid  = threadIdx.x;
    const int wid  = tid >> 5;
    const int lane = tid & 31;
    const int n0   = blockIdx.x * 16;       // 16 spiral rows per block

    // Re-zero g_cnt for the next call (192*256 = 49152 threads cover NU)
    {
        int i = blockIdx.x * 256 + tid;
        if (i < NU) g_cnt[i] = 0;
    }

    int* Sg = reinterpret_cast<int*>(smraw + SM_SG);

    if (tid == 0) {
        mbar_init(smb + SM_MBAR + 0,  1);
        mbar_init(smb + SM_MBAR + 8,  1);
        mbar_init(smb + SM_MBAR + 16, 1);
    }

    // Stage W hi/lo (pre-swizzled) via cp.async
    {
        const char* wh = reinterpret_cast<const char*>(g_wh);
        const char* wl = reinterpret_cast<const char*>(g_wl);
        for (int i = tid; i < SP * 4096 / 16; i += 256) {
            cp16(smb + SM_W + i * 16, wh + i * 16);
            cp16(smb + SM_W + SP * 4096 + i * 16, wl + i * 16);
        }
        CP_COMMIT();
    }
    // 16 rows x 9 spiral indices (contiguous)
    if (tid < 144) Sg[tid] = __ldg(sidx + (size_t)n0 * SP + tid);
    __syncthreads();   // Sg + mbarrier init visible

    // Stage gather: 16 bulk copies of 2KB (threads 0..15), single expect_tx
    auto gather = [&](int s) {
        int buf = s % 3;
        uint32_t mbar = smb + SM_MBAR + buf * 8;
        if (tid == 0) mbar_expect_tx(mbar, 16 * 2048);
        if (tid < 16) {
            int idx = Sg[tid * SP + s];
            bulk_g2s(smb + SM_A + buf * ABUF + tid * 2048,
                     g_pool + (size_t)idx * 2048, 2048, mbar);
        }
    };

    gather(0);
    gather(1);
    gather(2);

    CP_WAIT(0);        // W landed
    __syncthreads();

    float acc[4][4];
#pragma unroll
    for (int i = 0; i < 4; i++)
#pragma unroll
        for (int j = 0; j < 4; j++) acc[i][j] = 0.f;

    // ldmatrix geometry: warp w covers GEMM rows w*16..w*16+15
    //   GEMM row = rl*8 + b  (rl: local spiral row, b: batch)
    //   lane: m8 = lane>>3 (matrix id), t8 = lane&7 (= batch b)
    //   rl = 2*wid + (m8&1);  k-half mk = m8>>1
    const int m8 = lane >> 3;
    const int t8 = lane & 7;
    const int rl = 2 * wid + (m8 & 1);
    const int mk = m8 >> 1;

#pragma unroll 1
    for (int s = 0; s < SP; s++) {
        mbar_wait(smb + SM_MBAR + (s % 3) * 8, (s / 3) & 1);

        uint32_t abase = smb + SM_A + (s % 3) * ABUF;
        uint32_t wbase = smb + SM_W + s * 4096;

#pragma unroll
        for (int ks = 0; ks < 4; ks++) {
            int unit = 2 * ks + mk;
            // A: chunk rl, batch t8, unit XOR-swizzled by batch
            uint32_t aaddr = abase + rl * 2048 + t8 * 128 + ((unit ^ t8) << 4);
            uint32_t ah[4], al[4];
            ldsm4(aaddr,        ah[0], ah[1], ah[2], ah[3]);
            ldsm4(aaddr + 1024, al[0], al[1], al[2], al[3]);   // lo plane
            uint32_t bh0[4], bh1[4], bl0[4], bl1[4];
#pragma unroll
            for (int nb = 0; nb < 2; nb++) {
                int nrow = nb * 16 + (m8 & 1) * 8 + t8;
                uint32_t baddr = wbase + nrow * 128 + ((unit ^ (nrow & 7)) << 4);
                uint32_t* bh = nb ? bh1 : bh0;
                uint32_t* bl = nb ? bl1 : bl0;
                ldsm4(baddr,             bh[0], bh[1], bh[2], bh[3]);
                ldsm4(baddr + SP * 4096, bl[0], bl[1], bl[2], bl[3]);
            }
            mma_bf16(acc[0], ah[0], ah[1], ah[2], ah[3], bh0[0], bh0[2]);
            mma_bf16(acc[1], ah[0], ah[1], ah[2], ah[3], bh0[1], bh0[3]);
            mma_bf16(acc[2], ah[0], ah[1], ah[2], ah[3], bh1[0], bh1[2]);
            mma_bf16(acc[3], ah[0], ah[1], ah[2], ah[3], bh1[1], bh1[3]);
            mma_bf16(acc[0], al[0], al[1], al[2], al[3], bh0[0], bh0[2]);
            mma_bf16(acc[1], al[0], al[1], al[2], al[3], bh0[1], bh0[3]);
            mma_bf16(acc[2], al[0], al[1], al[2], al[3], bh1[0], bh1[2]);
            mma_bf16(acc[3], al[0], al[1], al[2], al[3], bh1[1], bh1[3]);
            mma_bf16(acc[0], ah[0], ah[1], ah[2], ah[3], bl0[0], bl0[2]);
            mma_bf16(acc[1], ah[0], ah[1], ah[2], ah[3], bl0[1], bl0[3]);
            mma_bf16(acc[2], ah[0], ah[1], ah[2], ah[3], bl1[0], bl1[2]);
            mma_bf16(acc[3], ah[0], ah[1], ah[2], ah[3], bl1[1], bl1[3]);
        }

        __syncthreads();   // all warps done reading buf (s%3)
        if (s + 3 < SP) gather(s + 3);
    }

    // Epilogue: GEMM row g = w*16 + (lane>>2) (+8): rl = g>>3, batch = g&7
    const int gr  = wid * 16 + (lane >> 2);
    const int col = (lane & 3) * 2;
    const int b0r = gr & 7;
    const int nr0 = n0 + (gr >> 3);
    const int nr1 = n0 + ((gr + 8) >> 3);
    float* po0 = out + ((size_t)b0r * NU + nr0) * CO;
    float* po1 = out + ((size_t)b0r * NU + nr1) * CO;
#pragma unroll
    for (int nt = 0; nt < 4; nt++) {
        int o = nt * 8 + col;
        float c0 = __ldg(bias + o), c1 = __ldg(bias + o + 1);
        float2 v0 = make_float2(fmaxf(acc[nt][0] + c0, 0.f), fmaxf(acc[nt][1] + c1, 0.f));
        float2 v1 = make_float2(fmaxf(acc[nt][2] + c0, 0.f), fmaxf(acc[nt][3] + c1, 0.f));
        *reinterpret_cast<float2*>(po0 + o) = v0;
        *reinterpret_cast<float2*>(po1 + o) = v1;
    }
}

// ---------------------------------------------------------------------------
// Launch (4 kernels; spiral_mma at absolute index 3 for ncu capture)
// ---------------------------------------------------------------------------
extern "C" void kernel_launch(void* const* d_in, const int* in_sizes, int n_in,
                              void* d_out, int out_size) {
    const float* x        = (const float*)d_in[0];
    const int*   up_rows  = (const int*)  d_in[1];
    const int*   up_cols  = (const int*)  d_in[2];
    const float* up_vals  = (const float*)d_in[3];
    const int*   sidx     = (const int*)  d_in[4];
    const float* weight   = (const float*)d_in[5];
    const float* bias     = (const float*)d_in[6];
    float*       out      = (float*)d_out;

    hist_rows<<<(NNZE + 255) / 256, 256>>>(up_rows);
    scan_fill<<<1, 1024>>>(up_rows, weight);
    gather_pool<<<(NU * 16) / 256, 256>>>(x, up_cols, up_vals);

    cudaFuncSetAttribute(spiral_mma,
                         cudaFuncAttributeMaxDynamicSharedMemorySize, SM_TOT);
    spiral_mma<<<NU / 16, 256, SM_TOT>>>(sidx, bias, out);
}

// round 9
// speedup vs baseline: 1.4014x; 1.1613x over previous
#include <cuda_runtime.h>
#include <cuda_bf16.h>
#include <cstdint>

// Problem constants
#define BB   8
#define ND   12288
#define NU   49152
#define CI   64
#define CO   32
#define SP   9
#define NNZE 147456
#define KTOT (SP * CI)   // 576

// ---------------------------------------------------------------------------
// Device scratch (statics zero-initialized; g_cnt re-zeroed by spiral_mma)
// ---------------------------------------------------------------------------
__device__ int g_cnt[NU];
__device__ int g_off[NU + 1];
__device__ int g_wp[NU];
__device__ int g_eid[NNZE];
// pooled: per row a 2KB chunk: [hi: b0..b7 x 128B | lo: b0..b7 x 128B],
// within (plane,b): 16B unit u stored at offset ((u ^ b) << 4)
__device__ __align__(256) unsigned char g_pool[(size_t)NU * 2048];
// weight, split bf16, [s][n=32][k=64] with 16B-unit XOR swizzle, ldmatrix-ready
__device__ __align__(256) unsigned short g_wh[SP * CO * CI];
__device__ __align__(256) unsigned short g_wl[SP * CO * CI];

// ---------------------------------------------------------------------------
// Launch 0: histogram of rows
// ---------------------------------------------------------------------------
__global__ void hist_rows(const int* __restrict__ rows) {
    int e = blockIdx.x * blockDim.x + threadIdx.x;
    if (e < NNZE) atomicAdd(&g_cnt[__ldg(rows + e)], 1);
}

// ---------------------------------------------------------------------------
// Launch 1: single-block scan + CSR fill + weight split/swizzle prepack
// ---------------------------------------------------------------------------
__global__ void __launch_bounds__(1024)
scan_fill(const int* __restrict__ rows, const float* __restrict__ weight) {
    __shared__ int warp_sums[32];
    const int t = threadIdx.x, lane = t & 31, w = t >> 5;

    // Weight prepack (independent)
    for (int i = t; i < SP * CO * CI; i += 1024) {
        int k = i & 63;
        int n = (i >> 6) & 31;
        int s = i >> 11;
        float v = __ldg(weight + n * KTOT + s * CI + k);
        __nv_bfloat16 hi = __float2bfloat16(v);
        __nv_bfloat16 lo = __float2bfloat16(v - __bfloat162float(hi));
        int unit = k >> 3;
        int within = (k * 2) & 15;
        int byte = s * 4096 + n * 128 + ((unit ^ (n & 7)) << 4) + within;
        g_wh[byte >> 1] = __bfloat16_as_ushort(hi);
        g_wl[byte >> 1] = __bfloat16_as_ushort(lo);
    }

    const int base = t * (NU / 1024);
    int local = 0;
#pragma unroll 4
    for (int j = 0; j < NU / 1024; j++) local += g_cnt[base + j];

    int v = local;
#pragma unroll
    for (int d = 1; d < 32; d <<= 1) {
        int n = __shfl_up_sync(0xffffffffu, v, d);
        if (lane >= d) v += n;
    }
    if (lane == 31) warp_sums[w] = v;
    __syncthreads();
    if (w == 0) {
        int s = warp_sums[lane];
#pragma unroll
        for (int d = 1; d < 32; d <<= 1) {
            int n = __shfl_up_sync(0xffffffffu, s, d);
            if (lane >= d) s += n;
        }
        warp_sums[lane] = s;
    }
    __syncthreads();

    int run = (v - local) + (w > 0 ? warp_sums[w - 1] : 0);
#pragma unroll 4
    for (int j = 0; j < NU / 1024; j++) {
        int c = g_cnt[base + j];
        g_off[base + j] = run;
        g_wp[base + j]  = run;
        run += c;
    }
    if (t == 1023) g_off[NU] = run;
    __syncthreads();

#pragma unroll 4
    for (int e = t; e < NNZE; e += 1024) {
        int p = atomicAdd(&g_wp[__ldg(rows + e)], 1);
        g_eid[p] = e;
    }
}

// ---------------------------------------------------------------------------
// Launch 2: gather-pool -> per-row 2KB chunks (hi/lo planes, batch-XOR units)
// ---------------------------------------------------------------------------
__global__ void __launch_bounds__(256)
gather_pool(const float* __restrict__ x,
            const int*   __restrict__ cols,
            const float* __restrict__ vals) {
    int gt  = blockIdx.x * blockDim.x + threadIdx.x;
    int row = gt >> 4;
    int c4  = gt & 15;
    if (row >= NU) return;

    int s = g_off[row];
    int e = g_off[row + 1];

    float4 acc[BB];
#pragma unroll
    for (int b = 0; b < BB; b++) acc[b] = make_float4(0.f, 0.f, 0.f, 0.f);

    for (int i = s; i < e; i++) {
        int   eid = g_eid[i];
        int   col = __ldg(cols + eid);
        float v   = __ldg(vals + eid);
        const float4* xp = reinterpret_cast<const float4*>(x) + (size_t)col * 16 + c4;
#pragma unroll
        for (int b = 0; b < BB; b++) {
            float4 xv = __ldg(xp + (size_t)b * (ND * 16));
            acc[b].x += v * xv.x; acc[b].y += v * xv.y;
            acc[b].z += v * xv.z; acc[b].w += v * xv.w;
        }
    }

    const int u = c4 >> 1;
    const int h = c4 & 1;
    unsigned char* chunk = g_pool + (size_t)row * 2048;
#pragma unroll
    for (int b = 0; b < BB; b++) {
        float f[4] = {acc[b].x, acc[b].y, acc[b].z, acc[b].w};
        ushort4 hh, ll;
        unsigned short* hp = &hh.x;
        unsigned short* lp = &ll.x;
#pragma unroll
        for (int j = 0; j < 4; j++) {
            __nv_bfloat16 hb = __float2bfloat16(f[j]);
            __nv_bfloat16 lb = __float2bfloat16(f[j] - __bfloat162float(hb));
            hp[j] = __bfloat16_as_ushort(hb);
            lp[j] = __bfloat16_as_ushort(lb);
        }
        int off = b * 128 + ((u ^ b) << 4) + h * 8;
        *reinterpret_cast<ushort4*>(chunk + off)        = hh;
        *reinterpret_cast<ushort4*>(chunk + 1024 + off) = ll;
    }
}

// ---------------------------------------------------------------------------
// Launch 3: fused spiral gather + mma.sync bf16-split GEMM + bias + relu.
// Block = 16 spiral rows x 8 batches = 128 GEMM rows x 32 outs.
// 2-deep ring; each slot = 32KB A (16 x 2KB bulk) + 8KB W stage tile
// (2 x 4KB bulk) on one mbarrier. smem 83KB -> 2 CTAs/SM.
// ---------------------------------------------------------------------------
#define ASLOT   32768
#define WSLOT   8192
#define SM_MBAR 0                           // 2 mbarriers
#define SM_SG   64                          // 144 ints (576 B)
#define SM_A    1024                        // 2 x 32KB
#define SM_W    (SM_A + 2 * ASLOT)          // 66560, 2 x 8KB
#define SM_TOT  (SM_W + 2 * WSLOT)          // 82944 B

__device__ __forceinline__ uint32_t smem_u32(const void* p) {
    uint32_t a;
    asm("{ .reg .u64 t; cvta.to.shared.u64 t, %1; cvt.u32.u64 %0, t; }" : "=r"(a) : "l"(p));
    return a;
}
__device__ __forceinline__ void mbar_init(uint32_t m, uint32_t cnt) {
    asm volatile("mbarrier.init.shared.b64 [%0], %1;" :: "r"(m), "r"(cnt) : "memory");
}
__device__ __forceinline__ void mbar_expect_tx(uint32_t m, uint32_t bytes) {
    asm volatile("mbarrier.arrive.expect_tx.shared.b64 _, [%0], %1;"
                 :: "r"(m), "r"(bytes) : "memory");
}
__device__ __forceinline__ void mbar_wait(uint32_t m, uint32_t parity) {
    asm volatile(
        "{\n\t.reg .pred P;\n"
        "W_%=:\n\t"
        "mbarrier.try_wait.parity.shared::cta.b64 P, [%0], %1;\n\t"
        "@!P bra W_%=;\n\t}"
        :: "r"(m), "r"(parity) : "memory");
}
__device__ __forceinline__ void bulk_g2s(uint32_t dst, const void* src,
                                         uint32_t bytes, uint32_t mbar) {
    asm volatile(
        "cp.async.bulk.shared::cluster.global.mbarrier::complete_tx::bytes "
        "[%0], [%1], %2, [%3];"
        :: "r"(dst), "l"(src), "r"(bytes), "r"(mbar) : "memory");
}
__device__ __forceinline__ void ldsm4(uint32_t addr, uint32_t& r0, uint32_t& r1,
                                      uint32_t& r2, uint32_t& r3) {
    asm volatile("ldmatrix.sync.aligned.m8n8.x4.shared.b16 {%0,%1,%2,%3}, [%4];"
                 : "=r"(r0), "=r"(r1), "=r"(r2), "=r"(r3) : "r"(addr));
}
__device__ __forceinline__ void mma_bf16(float* c, uint32_t a0, uint32_t a1,
                                         uint32_t a2, uint32_t a3,
                                         uint32_t b0, uint32_t b1) {
    asm volatile(
        "mma.sync.aligned.m16n8k16.row.col.f32.bf16.bf16.f32 "
        "{%0,%1,%2,%3}, {%4,%5,%6,%7}, {%8,%9}, {%0,%1,%2,%3};"
        : "+f"(c[0]), "+f"(c[1]), "+f"(c[2]), "+f"(c[3])
        : "r"(a0), "r"(a1), "r"(a2), "r"(a3), "r"(b0), "r"(b1));
}

__global__ void __launch_bounds__(256, 2)
spiral_mma(const int*   __restrict__ sidx,
           const float* __restrict__ bias,
           float*       __restrict__ out) {
    extern __shared__ char smraw[];
    uint32_t smb = smem_u32(smraw);

    const int tid  = threadIdx.x;
    const int wid  = tid >> 5;
    const int lane = tid & 31;
    const int n0   = blockIdx.x * 16;

    // Re-zero g_cnt for the next call
    {
        int i = blockIdx.x * 256 + tid;
        if (i < NU) g_cnt[i] = 0;
    }

    int* Sg = reinterpret_cast<int*>(smraw + SM_SG);

    if (tid == 0) {
        mbar_init(smb + SM_MBAR + 0, 1);
        mbar_init(smb + SM_MBAR + 8, 1);
    }
    if (tid < 144) Sg[tid] = __ldg(sidx + (size_t)n0 * SP + tid);
    __syncthreads();   // Sg + mbarrier init visible

    // Stage gather: slot = s&1; 16 x 2KB A rows + 4KB W-hi + 4KB W-lo
    auto gather = [&](int s) {
        int slot = s & 1;
        uint32_t mbar = smb + SM_MBAR + slot * 8;
        if (tid == 0) mbar_expect_tx(mbar, ASLOT + WSLOT);
        if (tid < 16) {
            int idx = Sg[tid * SP + s];
            bulk_g2s(smb + SM_A + slot * ASLOT + tid * 2048,
                     g_pool + (size_t)idx * 2048, 2048, mbar);
        } else if (tid == 16) {
            bulk_g2s(smb + SM_W + slot * WSLOT,
                     reinterpret_cast<const char*>(g_wh) + s * 4096, 4096, mbar);
        } else if (tid == 17) {
            bulk_g2s(smb + SM_W + slot * WSLOT + 4096,
                     reinterpret_cast<const char*>(g_wl) + s * 4096, 4096, mbar);
        }
    };

    gather(0);
    gather(1);

    float acc[4][4];
#pragma unroll
    for (int i = 0; i < 4; i++)
#pragma unroll
        for (int j = 0; j < 4; j++) acc[i][j] = 0.f;

    // ldmatrix geometry (see round-8 comments)
    const int m8 = lane >> 3;
    const int t8 = lane & 7;
    const int rl = 2 * wid + (m8 & 1);
    const int mk = m8 >> 1;

#pragma unroll 1
    for (int s = 0; s < SP; s++) {
        int slot = s & 1;
        mbar_wait(smb + SM_MBAR + slot * 8, (s >> 1) & 1);

        uint32_t abase = smb + SM_A + slot * ASLOT;
        uint32_t wbase = smb + SM_W + slot * WSLOT;

#pragma unroll
        for (int ks = 0; ks < 4; ks++) {
            int unit = 2 * ks + mk;
            uint32_t aaddr = abase + rl * 2048 + t8 * 128 + ((unit ^ t8) << 4);
            uint32_t ah[4], al[4];
            ldsm4(aaddr,        ah[0], ah[1], ah[2], ah[3]);
            ldsm4(aaddr + 1024, al[0], al[1], al[2], al[3]);
            uint32_t bh0[4], bh1[4], bl0[4], bl1[4];
#pragma unroll
            for (int nb = 0; nb < 2; nb++) {
                int nrow = nb * 16 + (m8 & 1) * 8 + t8;
                uint32_t baddr = wbase + nrow * 128 + ((unit ^ (nrow & 7)) << 4);
                uint32_t* bh = nb ? bh1 : bh0;
                uint32_t* bl = nb ? bl1 : bl0;
                ldsm4(baddr,        bh[0], bh[1], bh[2], bh[3]);
                ldsm4(baddr + 4096, bl[0], bl[1], bl[2], bl[3]);
            }
            mma_bf16(acc[0], ah[0], ah[1], ah[2], ah[3], bh0[0], bh0[2]);
            mma_bf16(acc[1], ah[0], ah[1], ah[2], ah[3], bh0[1], bh0[3]);
            mma_bf16(acc[2], ah[0], ah[1], ah[2], ah[3], bh1[0], bh1[2]);
            mma_bf16(acc[3], ah[0], ah[1], ah[2], ah[3], bh1[1], bh1[3]);
            mma_bf16(acc[0], al[0], al[1], al[2], al[3], bh0[0], bh0[2]);
            mma_bf16(acc[1], al[0], al[1], al[2], al[3], bh0[1], bh0[3]);
            mma_bf16(acc[2], al[0], al[1], al[2], al[3], bh1[0], bh1[2]);
            mma_bf16(acc[3], al[0], al[1], al[2], al[3], bh1[1], bh1[3]);
            mma_bf16(acc[0], ah[0], ah[1], ah[2], ah[3], bl0[0], bl0[2]);
            mma_bf16(acc[1], ah[0], ah[1], ah[2], ah[3], bl0[1], bl0[3]);
            mma_bf16(acc[2], ah[0], ah[1], ah[2], ah[3], bl1[0], bl1[2]);
            mma_bf16(acc[3], ah[0], ah[1], ah[2], ah[3], bl1[1], bl1[3]);
        }

        __syncthreads();   // all warps done reading slot
        if (s + 2 < SP) gather(s + 2);
    }

    // Epilogue
    const int gr  = wid * 16 + (lane >> 2);
    const int col = (lane & 3) * 2;
    const int b0r = gr & 7;
    const int nr0 = n0 + (gr >> 3);
    const int nr1 = n0 + ((gr + 8) >> 3);
    float* po0 = out + ((size_t)b0r * NU + nr0) * CO;
    float* po1 = out + ((size_t)b0r * NU + nr1) * CO;
#pragma unroll
    for (int nt = 0; nt < 4; nt++) {
        int o = nt * 8 + col;
        float c0 = __ldg(bias + o), c1 = __ldg(bias + o + 1);
        float2 v0 = make_float2(fmaxf(acc[nt][0] + c0, 0.f), fmaxf(acc[nt][1] + c1, 0.f));
        float2 v1 = make_float2(fmaxf(acc[nt][2] + c0, 0.f), fmaxf(acc[nt][3] + c1, 0.f));
        *reinterpret_cast<float2*>(po0 + o) = v0;
        *reinterpret_cast<float2*>(po1 + o) = v1;
    }
}

// ---------------------------------------------------------------------------
// Launch (4 kernels; spiral_mma at absolute index 3 for ncu capture)
// ---------------------------------------------------------------------------
extern "C" void kernel_launch(void* const* d_in, const int* in_sizes, int n_in,
                              void* d_out, int out_size) {
    const float* x        = (const float*)d_in[0];
    const int*   up_rows  = (const int*)  d_in[1];
    const int*   up_cols  = (const int*)  d_in[2];
    const float* up_vals  = (const float*)d_in[3];
    const int*   sidx     = (const int*)  d_in[4];
    const float* weight   = (const float*)d_in[5];
    const float* bias     = (const float*)d_in[6];
    float*       out      = (float*)d_out;

    hist_rows<<<(NNZE + 255) / 256, 256>>>(up_rows);
    scan_fill<<<1, 1024>>>(up_rows, weight);
    gather_pool<<<(NU * 16) / 256, 256>>>(x, up_cols, up_vals);

    cudaFuncSetAttribute(spiral_mma,
                         cudaFuncAttributeMaxDynamicSharedMemorySize, SM_TOT);
    spiral_mma<<<NU / 16, 256, SM_TOT>>>(sidx, bias, out);
}

// round 10
// speedup vs baseline: 2.1420x; 1.5286x over previous
#include <cuda_runtime.h>
#include <cuda_bf16.h>
#include <cstdint>

// Problem constants
#define BB   8
#define ND   12288
#define NU   49152
#define CI   64
#define CO   32
#define SP   9
#define NNZE 147456
#define KTOT (SP * CI)   // 576

// ---------------------------------------------------------------------------
// Device scratch (statics zero-initialized; g_cnt re-zeroed by spiral_mma)
// ---------------------------------------------------------------------------
__device__ int g_cnt[NU];
__device__ int g_off[NU + 1];
__device__ int g_wp[NU];
__device__ int g_eid[NNZE];
// pooled: per row a 2KB chunk: [hi: b0..b7 x 128B | lo: b0..b7 x 128B],
// within (plane,b): 16B unit u stored at offset ((u ^ b) << 4)
__device__ __align__(256) unsigned char g_pool[(size_t)NU * 2048];
// weight, split bf16, [s][n=32][k=64] with 16B-unit XOR swizzle, ldmatrix-ready
__device__ __align__(256) unsigned short g_wh[SP * CO * CI];
__device__ __align__(256) unsigned short g_wl[SP * CO * CI];

// ---------------------------------------------------------------------------
// Launch 0: histogram of rows + weight split/swizzle prepack (multi-block)
// ---------------------------------------------------------------------------
__global__ void hist_prep(const int* __restrict__ rows,
                          const float* __restrict__ weight) {
    int i = blockIdx.x * blockDim.x + threadIdx.x;
    if (i < NNZE) atomicAdd(&g_cnt[__ldg(rows + i)], 1);
    if (i < SP * CO * CI) {
        int k = i & 63;
        int n = (i >> 6) & 31;
        int s = i >> 11;
        float v = __ldg(weight + n * KTOT + s * CI + k);
        __nv_bfloat16 hi = __float2bfloat16(v);
        __nv_bfloat16 lo = __float2bfloat16(v - __bfloat162float(hi));
        int unit = k >> 3;
        int within = (k * 2) & 15;
        int byte = s * 4096 + n * 128 + ((unit ^ (n & 7)) << 4) + within;
        g_wh[byte >> 1] = __bfloat16_as_ushort(hi);
        g_wl[byte >> 1] = __bfloat16_as_ushort(lo);
    }
}

// ---------------------------------------------------------------------------
// Launch 1: single-block exclusive scan of counts -> g_off, g_wp
// ---------------------------------------------------------------------------
__global__ void __launch_bounds__(1024)
scan_off() {
    __shared__ int warp_sums[32];
    const int t = threadIdx.x, lane = t & 31, w = t >> 5;
    const int base = t * (NU / 1024);

    int local = 0;
#pragma unroll 4
    for (int j = 0; j < NU / 1024; j++) local += g_cnt[base + j];

    int v = local;
#pragma unroll
    for (int d = 1; d < 32; d <<= 1) {
        int n = __shfl_up_sync(0xffffffffu, v, d);
        if (lane >= d) v += n;
    }
    if (lane == 31) warp_sums[w] = v;
    __syncthreads();
    if (w == 0) {
        int s = warp_sums[lane];
#pragma unroll
        for (int d = 1; d < 32; d <<= 1) {
            int n = __shfl_up_sync(0xffffffffu, s, d);
            if (lane >= d) s += n;
        }
        warp_sums[lane] = s;
    }
    __syncthreads();

    int run = (v - local) + (w > 0 ? warp_sums[w - 1] : 0);
#pragma unroll 4
    for (int j = 0; j < NU / 1024; j++) {
        int c = g_cnt[base + j];
        g_off[base + j] = run;
        g_wp[base + j]  = run;
        run += c;
    }
    if (t == 1023) g_off[NU] = run;
}

// ---------------------------------------------------------------------------
// Launch 2: CSR fill (multi-block)
// ---------------------------------------------------------------------------
__global__ void fill_eid(const int* __restrict__ rows) {
    int e = blockIdx.x * blockDim.x + threadIdx.x;
    if (e < NNZE) {
        int p = atomicAdd(&g_wp[__ldg(rows + e)], 1);
        g_eid[p] = e;
    }
}

// ---------------------------------------------------------------------------
// Launch 3: gather-pool -> per-row 2KB chunks (hi/lo planes, batch-XOR units)
// ---------------------------------------------------------------------------
__global__ void __launch_bounds__(256)
gather_pool(const float* __restrict__ x,
            const int*   __restrict__ cols,
            const float* __restrict__ vals) {
    int gt  = blockIdx.x * blockDim.x + threadIdx.x;
    int row = gt >> 4;
    int c4  = gt & 15;
    if (row >= NU) return;

    int s = g_off[row];
    int e = g_off[row + 1];

    float4 acc[BB];
#pragma unroll
    for (int b = 0; b < BB; b++) acc[b] = make_float4(0.f, 0.f, 0.f, 0.f);

    for (int i = s; i < e; i++) {
        int   eid = g_eid[i];
        int   col = __ldg(cols + eid);
        float v   = __ldg(vals + eid);
        const float4* xp = reinterpret_cast<const float4*>(x) + (size_t)col * 16 + c4;
#pragma unroll
        for (int b = 0; b < BB; b++) {
            float4 xv = __ldg(xp + (size_t)b * (ND * 16));
            acc[b].x += v * xv.x; acc[b].y += v * xv.y;
            acc[b].z += v * xv.z; acc[b].w += v * xv.w;
        }
    }

    const int u = c4 >> 1;
    const int h = c4 & 1;
    unsigned char* chunk = g_pool + (size_t)row * 2048;
#pragma unroll
    for (int b = 0; b < BB; b++) {
        float f[4] = {acc[b].x, acc[b].y, acc[b].z, acc[b].w};
        ushort4 hh, ll;
        unsigned short* hp = &hh.x;
        unsigned short* lp = &ll.x;
#pragma unroll
        for (int j = 0; j < 4; j++) {
            __nv_bfloat16 hb = __float2bfloat16(f[j]);
            __nv_bfloat16 lb = __float2bfloat16(f[j] - __bfloat162float(hb));
            hp[j] = __bfloat16_as_ushort(hb);
            lp[j] = __bfloat16_as_ushort(lb);
        }
        int off = b * 128 + ((u ^ b) << 4) + h * 8;
        *reinterpret_cast<ushort4*>(chunk + off)        = hh;
        *reinterpret_cast<ushort4*>(chunk + 1024 + off) = ll;
    }
}

// ---------------------------------------------------------------------------
// Launch 4: fused spiral gather + mma.sync bf16-split GEMM + bias + relu.
// (unchanged from round 9: 146us, tensor 49%, 2 CTAs/SM)
// ---------------------------------------------------------------------------
#define ASLOT   32768
#define WSLOT   8192
#define SM_MBAR 0
#define SM_SG   64
#define SM_A    1024
#define SM_W    (SM_A + 2 * ASLOT)
#define SM_TOT  (SM_W + 2 * WSLOT)          // 82944 B

__device__ __forceinline__ uint32_t smem_u32(const void* p) {
    uint32_t a;
    asm("{ .reg .u64 t; cvta.to.shared.u64 t, %1; cvt.u32.u64 %0, t; }" : "=r"(a) : "l"(p));
    return a;
}
__device__ __forceinline__ void mbar_init(uint32_t m, uint32_t cnt) {
    asm volatile("mbarrier.init.shared.b64 [%0], %1;" :: "r"(m), "r"(cnt) : "memory");
}
__device__ __forceinline__ void mbar_expect_tx(uint32_t m, uint32_t bytes) {
    asm volatile("mbarrier.arrive.expect_tx.shared.b64 _, [%0], %1;"
                 :: "r"(m), "r"(bytes) : "memory");
}
__device__ __forceinline__ void mbar_wait(uint32_t m, uint32_t parity) {
    asm volatile(
        "{\n\t.reg .pred P;\n"
        "W_%=:\n\t"
        "mbarrier.try_wait.parity.shared::cta.b64 P, [%0], %1;\n\t"
        "@!P bra W_%=;\n\t}"
        :: "r"(m), "r"(parity) : "memory");
}
__device__ __forceinline__ void bulk_g2s(uint32_t dst, const void* src,
                                         uint32_t bytes, uint32_t mbar) {
    asm volatile(
        "cp.async.bulk.shared::cluster.global.mbarrier::complete_tx::bytes "
        "[%0], [%1], %2, [%3];"
        :: "r"(dst), "l"(src), "r"(bytes), "r"(mbar) : "memory");
}
__device__ __forceinline__ void ldsm4(uint32_t addr, uint32_t& r0, uint32_t& r1,
                                      uint32_t& r2, uint32_t& r3) {
    asm volatile("ldmatrix.sync.aligned.m8n8.x4.shared.b16 {%0,%1,%2,%3}, [%4];"
                 : "=r"(r0), "=r"(r1), "=r"(r2), "=r"(r3) : "r"(addr));
}
__device__ __forceinline__ void mma_bf16(float* c, uint32_t a0, uint32_t a1,
                                         uint32_t a2, uint32_t a3,
                                         uint32_t b0, uint32_t b1) {
    asm volatile(
        "mma.sync.aligned.m16n8k16.row.col.f32.bf16.bf16.f32 "
        "{%0,%1,%2,%3}, {%4,%5,%6,%7}, {%8,%9}, {%0,%1,%2,%3};"
        : "+f"(c[0]), "+f"(c[1]), "+f"(c[2]), "+f"(c[3])
        : "r"(a0), "r"(a1), "r"(a2), "r"(a3), "r"(b0), "r"(b1));
}

__global__ void __launch_bounds__(256, 2)
spiral_mma(const int*   __restrict__ sidx,
           const float* __restrict__ bias,
           float*       __restrict__ out) {
    extern __shared__ char smraw[];
    uint32_t smb = smem_u32(smraw);

    const int tid  = threadIdx.x;
    const int wid  = tid >> 5;
    const int lane = tid & 31;
    const int n0   = blockIdx.x * 16;

    // Re-zero g_cnt for the next call
    {
        int i = blockIdx.x * 256 + tid;
        if (i < NU) g_cnt[i] = 0;
    }

    int* Sg = reinterpret_cast<int*>(smraw + SM_SG);

    if (tid == 0) {
        mbar_init(smb + SM_MBAR + 0, 1);
        mbar_init(smb + SM_MBAR + 8, 1);
    }
    if (tid < 144) Sg[tid] = __ldg(sidx + (size_t)n0 * SP + tid);
    __syncthreads();

    auto gather = [&](int s) {
        int slot = s & 1;
        uint32_t mbar = smb + SM_MBAR + slot * 8;
        if (tid == 0) mbar_expect_tx(mbar, ASLOT + WSLOT);
        if (tid < 16) {
            int idx = Sg[tid * SP + s];
            bulk_g2s(smb + SM_A + slot * ASLOT + tid * 2048,
                     g_pool + (size_t)idx * 2048, 2048, mbar);
        } else if (tid == 16) {
            bulk_g2s(smb + SM_W + slot * WSLOT,
                     reinterpret_cast<const char*>(g_wh) + s * 4096, 4096, mbar);
        } else if (tid == 17) {
            bulk_g2s(smb + SM_W + slot * WSLOT + 4096,
                     reinterpret_cast<const char*>(g_wl) + s * 4096, 4096, mbar);
        }
    };

    gather(0);
    gather(1);

    float acc[4][4];
#pragma unroll
    for (int i = 0; i < 4; i++)
#pragma unroll
        for (int j = 0; j < 4; j++) acc[i][j] = 0.f;

    const int m8 = lane >> 3;
    const int t8 = lane & 7;
    const int rl = 2 * wid + (m8 & 1);
    const int mk = m8 >> 1;

#pragma unroll 1
    for (int s = 0; s < SP; s++) {
        int slot = s & 1;
        mbar_wait(smb + SM_MBAR + slot * 8, (s >> 1) & 1);

        uint32_t abase = smb + SM_A + slot * ASLOT;
        uint32_t wbase = smb + SM_W + slot * WSLOT;

#pragma unroll
        for (int ks = 0; ks < 4; ks++) {
            int unit = 2 * ks + mk;
            uint32_t aaddr = abase + rl * 2048 + t8 * 128 + ((unit ^ t8) << 4);
            uint32_t ah[4], al[4];
            ldsm4(aaddr,        ah[0], ah[1], ah[2], ah[3]);
            ldsm4(aaddr + 1024, al[0], al[1], al[2], al[3]);
            uint32_t bh0[4], bh1[4], bl0[4], bl1[4];
#pragma unroll
            for (int nb = 0; nb < 2; nb++) {
                int nrow = nb * 16 + (m8 & 1) * 8 + t8;
                uint32_t baddr = wbase + nrow * 128 + ((unit ^ (nrow & 7)) << 4);
                uint32_t* bh = nb ? bh1 : bh0;
                uint32_t* bl = nb ? bl1 : bl0;
                ldsm4(baddr,        bh[0], bh[1], bh[2], bh[3]);
                ldsm4(baddr + 4096, bl[0], bl[1], bl[2], bl[3]);
            }
            mma_bf16(acc[0], ah[0], ah[1], ah[2], ah[3], bh0[0], bh0[2]);
            mma_bf16(acc[1], ah[0], ah[1], ah[2], ah[3], bh0[1], bh0[3]);
            mma_bf16(acc[2], ah[0], ah[1], ah[2], ah[3], bh1[0], bh1[2]);
            mma_bf16(acc[3], ah[0], ah[1], ah[2], ah[3], bh1[1], bh1[3]);
            mma_bf16(acc[0], al[0], al[1], al[2], al[3], bh0[0], bh0[2]);
            mma_bf16(acc[1], al[0], al[1], al[2], al[3], bh0[1], bh0[3]);
            mma_bf16(acc[2], al[0], al[1], al[2], al[3], bh1[0], bh1[2]);
            mma_bf16(acc[3], al[0], al[1], al[2], al[3], bh1[1], bh1[3]);
            mma_bf16(acc[0], ah[0], ah[1], ah[2], ah[3], bl0[0], bl0[2]);
            mma_bf16(acc[1], ah[0], ah[1], ah[2], ah[3], bl0[1], bl0[3]);
            mma_bf16(acc[2], ah[0], ah[1], ah[2], ah[3], bl1[0], bl1[2]);
            mma_bf16(acc[3], ah[0], ah[1], ah[2], ah[3], bl1[1], bl1[3]);
        }

        __syncthreads();
        if (s + 2 < SP) gather(s + 2);
    }

    const int gr  = wid * 16 + (lane >> 2);
    const int col = (lane & 3) * 2;
    const int b0r = gr & 7;
    const int nr0 = n0 + (gr >> 3);
    const int nr1 = n0 + ((gr + 8) >> 3);
    float* po0 = out + ((size_t)b0r * NU + nr0) * CO;
    float* po1 = out + ((size_t)b0r * NU + nr1) * CO;
#pragma unroll
    for (int nt = 0; nt < 4; nt++) {
        int o = nt * 8 + col;
        float c0 = __ldg(bias + o), c1 = __ldg(bias + o + 1);
        float2 v0 = make_float2(fmaxf(acc[nt][0] + c0, 0.f), fmaxf(acc[nt][1] + c1, 0.f));
        float2 v1 = make_float2(fmaxf(acc[nt][2] + c0, 0.f), fmaxf(acc[nt][3] + c1, 0.f));
        *reinterpret_cast<float2*>(po0 + o) = v0;
        *reinterpret_cast<float2*>(po1 + o) = v1;
    }
}

// ---------------------------------------------------------------------------
// Launch (5 kernels; gather_pool at ncu capture index 3)
// ---------------------------------------------------------------------------
extern "C" void kernel_launch(void* const* d_in, const int* in_sizes, int n_in,
                              void* d_out, int out_size) {
    const float* x        = (const float*)d_in[0];
    const int*   up_rows  = (const int*)  d_in[1];
    const int*   up_cols  = (const int*)  d_in[2];
    const float* up_vals  = (const float*)d_in[3];
    const int*   sidx     = (const int*)  d_in[4];
    const float* weight   = (const float*)d_in[5];
    const float* bias     = (const float*)d_in[6];
    float*       out      = (float*)d_out;

    hist_prep<<<(NNZE + 255) / 256, 256>>>(up_rows, weight);
    scan_off<<<1, 1024>>>();
    fill_eid<<<(NNZE + 255) / 256, 256>>>(up_rows);
    gather_pool<<<(NU * 16) / 256, 256>>>(x, up_cols, up_vals);

    cudaFuncSetAttribute(spiral_mma,
                         cudaFuncAttributeMaxDynamicSharedMemorySize, SM_TOT);
    spiral_mma<<<NU / 16, 256, SM_TOT>>>(sidx, bias, out);
}

// round 11
// speedup vs baseline: 3.2357x; 1.5106x over previous
#include <cuda_runtime.h>
#include <cuda_bf16.h>
#include <cstdint>

// Problem constants
#define BB   8
#define ND   12288
#define NU   49152
#define CI   64
#define CO   32
#define SP   9
#define NNZE 147456
#define KTOT (SP * CI)   // 576
#define ELLW 32          // padded entries per row (lambda=3; overflow P ~1e-21)

// ---------------------------------------------------------------------------
// Device scratch (statics zero-initialized; g_cnt re-zeroed by spiral_mma)
// ---------------------------------------------------------------------------
__device__ int   g_cnt[NU];
__device__ int   g_ellc[NU * ELLW];     // col per slot
__device__ float g_ellv[NU * ELLW];     // val per slot
// pooled: per row a 2KB chunk: [hi: b0..b7 x 128B | lo: b0..b7 x 128B],
// within (plane,b): 16B unit u stored at offset ((u ^ b) << 4)
__device__ __align__(256) unsigned char g_pool[(size_t)NU * 2048];
// weight, split bf16, [s][n=32][k=64] with 16B-unit XOR swizzle, ldmatrix-ready
__device__ __align__(256) unsigned short g_wh[SP * CO * CI];
__device__ __align__(256) unsigned short g_wl[SP * CO * CI];

// ---------------------------------------------------------------------------
// Launch 0: ELL build (hist+fill fused) + weight split/swizzle prepack
// ---------------------------------------------------------------------------
__global__ void ell_fill(const int*   __restrict__ rows,
                         const int*   __restrict__ cols,
                         const float* __restrict__ vals,
                         const float* __restrict__ weight) {
    int i = blockIdx.x * blockDim.x + threadIdx.x;
    if (i < NNZE) {
        int row = __ldg(rows + i);
        int p = atomicAdd(&g_cnt[row], 1);
        if (p < ELLW) {
            g_ellc[row * ELLW + p] = __ldg(cols + i);
            g_ellv[row * ELLW + p] = __ldg(vals + i);
        }
    }
    if (i < SP * CO * CI) {
        int k = i & 63;
        int n = (i >> 6) & 31;
        int s = i >> 11;
        float v = __ldg(weight + n * KTOT + s * CI + k);
        __nv_bfloat16 hi = __float2bfloat16(v);
        __nv_bfloat16 lo = __float2bfloat16(v - __bfloat162float(hi));
        int unit = k >> 3;
        int within = (k * 2) & 15;
        int byte = s * 4096 + n * 128 + ((unit ^ (n & 7)) << 4) + within;
        g_wh[byte >> 1] = __bfloat16_as_ushort(hi);
        g_wl[byte >> 1] = __bfloat16_as_ushort(lo);
    }
}

// ---------------------------------------------------------------------------
// Launch 1: gather-pool from ELL -> per-row 2KB chunks (hi/lo, batch-XOR)
// thread = (row, c4)
// ---------------------------------------------------------------------------
__global__ void __launch_bounds__(256)
gather_pool(const float* __restrict__ x) {
    int gt  = blockIdx.x * blockDim.x + threadIdx.x;
    int row = gt >> 4;
    int c4  = gt & 15;
    if (row >= NU) return;

    int cnt = g_cnt[row];
    if (cnt > ELLW) cnt = ELLW;

    float4 acc[BB];
#pragma unroll
    for (int b = 0; b < BB; b++) acc[b] = make_float4(0.f, 0.f, 0.f, 0.f);

    const int*   ec = g_ellc + row * ELLW;
    const float* ev = g_ellv + row * ELLW;
    for (int i = 0; i < cnt; i++) {
        int   col = __ldg(ec + i);
        float v   = __ldg(ev + i);
        const float4* xp = reinterpret_cast<const float4*>(x) + (size_t)col * 16 + c4;
#pragma unroll
        for (int b = 0; b < BB; b++) {
            float4 xv = __ldg(xp + (size_t)b * (ND * 16));
            acc[b].x += v * xv.x; acc[b].y += v * xv.y;
            acc[b].z += v * xv.z; acc[b].w += v * xv.w;
        }
    }

    const int u = c4 >> 1;
    const int h = c4 & 1;
    unsigned char* chunk = g_pool + (size_t)row * 2048;
#pragma unroll
    for (int b = 0; b < BB; b++) {
        float f[4] = {acc[b].x, acc[b].y, acc[b].z, acc[b].w};
        ushort4 hh, ll;
        unsigned short* hp = &hh.x;
        unsigned short* lp = &ll.x;
#pragma unroll
        for (int j = 0; j < 4; j++) {
            __nv_bfloat16 hb = __float2bfloat16(f[j]);
            __nv_bfloat16 lb = __float2bfloat16(f[j] - __bfloat162float(hb));
            hp[j] = __bfloat16_as_ushort(hb);
            lp[j] = __bfloat16_as_ushort(lb);
        }
        int off = b * 128 + ((u ^ b) << 4) + h * 8;
        *reinterpret_cast<ushort4*>(chunk + off)        = hh;
        *reinterpret_cast<ushort4*>(chunk + 1024 + off) = ll;
    }
}

// ---------------------------------------------------------------------------
// Launch 2: fused spiral gather + mma.sync bf16-split GEMM + bias + relu.
// (unchanged from round 9: 146us, tensor 49%, 2 CTAs/SM)
// Also re-zeros g_cnt for the next call.
// ---------------------------------------------------------------------------
#define ASLOT   32768
#define WSLOT   8192
#define SM_MBAR 0
#define SM_SG   64
#define SM_A    1024
#define SM_W    (SM_A + 2 * ASLOT)
#define SM_TOT  (SM_W + 2 * WSLOT)          // 82944 B

__device__ __forceinline__ uint32_t smem_u32(const void* p) {
    uint32_t a;
    asm("{ .reg .u64 t; cvta.to.shared.u64 t, %1; cvt.u32.u64 %0, t; }" : "=r"(a) : "l"(p));
    return a;
}
__device__ __forceinline__ void mbar_init(uint32_t m, uint32_t cnt) {
    asm volatile("mbarrier.init.shared.b64 [%0], %1;" :: "r"(m), "r"(cnt) : "memory");
}
__device__ __forceinline__ void mbar_expect_tx(uint32_t m, uint32_t bytes) {
    asm volatile("mbarrier.arrive.expect_tx.shared.b64 _, [%0], %1;"
                 :: "r"(m), "r"(bytes) : "memory");
}
__device__ __forceinline__ void mbar_wait(uint32_t m, uint32_t parity) {
    asm volatile(
        "{\n\t.reg .pred P;\n"
        "W_%=:\n\t"
        "mbarrier.try_wait.parity.shared::cta.b64 P, [%0], %1;\n\t"
        "@!P bra W_%=;\n\t}"
        :: "r"(m), "r"(parity) : "memory");
}
__device__ __forceinline__ void bulk_g2s(uint32_t dst, const void* src,
                                         uint32_t bytes, uint32_t mbar) {
    asm volatile(
        "cp.async.bulk.shared::cluster.global.mbarrier::complete_tx::bytes "
        "[%0], [%1], %2, [%3];"
        :: "r"(dst), "l"(src), "r"(bytes), "r"(mbar) : "memory");
}
__device__ __forceinline__ void ldsm4(uint32_t addr, uint32_t& r0, uint32_t& r1,
                                      uint32_t& r2, uint32_t& r3) {
    asm volatile("ldmatrix.sync.aligned.m8n8.x4.shared.b16 {%0,%1,%2,%3}, [%4];"
                 : "=r"(r0), "=r"(r1), "=r"(r2), "=r"(r3) : "r"(addr));
}
__device__ __forceinline__ void mma_bf16(float* c, uint32_t a0, uint32_t a1,
                                         uint32_t a2, uint32_t a3,
                                         uint32_t b0, uint32_t b1) {
    asm volatile(
        "mma.sync.aligned.m16n8k16.row.col.f32.bf16.bf16.f32 "
        "{%0,%1,%2,%3}, {%4,%5,%6,%7}, {%8,%9}, {%0,%1,%2,%3};"
        : "+f"(c[0]), "+f"(c[1]), "+f"(c[2]), "+f"(c[3])
        : "r"(a0), "r"(a1), "r"(a2), "r"(a3), "r"(b0), "r"(b1));
}

__global__ void __launch_bounds__(256, 2)
spiral_mma(const int*   __restrict__ sidx,
           const float* __restrict__ bias,
           float*       __restrict__ out) {
    extern __shared__ char smraw[];
    uint32_t smb = smem_u32(smraw);

    const int tid  = threadIdx.x;
    const int wid  = tid >> 5;
    const int lane = tid & 31;
    const int n0   = blockIdx.x * 16;

    // Re-zero g_cnt for the next call
    {
        int i = blockIdx.x * 256 + tid;
        if (i < NU) g_cnt[i] = 0;
    }

    int* Sg = reinterpret_cast<int*>(smraw + SM_SG);

    if (tid == 0) {
        mbar_init(smb + SM_MBAR + 0, 1);
        mbar_init(smb + SM_MBAR + 8, 1);
    }
    if (tid < 144) Sg[tid] = __ldg(sidx + (size_t)n0 * SP + tid);
    __syncthreads();

    auto gather = [&](int s) {
        int slot = s & 1;
        uint32_t mbar = smb + SM_MBAR + slot * 8;
        if (tid == 0) mbar_expect_tx(mbar, ASLOT + WSLOT);
        if (tid < 16) {
            int idx = Sg[tid * SP + s];
            bulk_g2s(smb + SM_A + slot * ASLOT + tid * 2048,
                     g_pool + (size_t)idx * 2048, 2048, mbar);
        } else if (tid == 16) {
            bulk_g2s(smb + SM_W + slot * WSLOT,
                     reinterpret_cast<const char*>(g_wh) + s * 4096, 4096, mbar);
        } else if (tid == 17) {
            bulk_g2s(smb + SM_W + slot * WSLOT + 4096,
                     reinterpret_cast<const char*>(g_wl) + s * 4096, 4096, mbar);
        }
    };

    gather(0);
    gather(1);

    float acc[4][4];
#pragma unroll
    for (int i = 0; i < 4; i++)
#pragma unroll
        for (int j = 0; j < 4; j++) acc[i][j] = 0.f;

    const int m8 = lane >> 3;
    const int t8 = lane & 7;
    const int rl = 2 * wid + (m8 & 1);
    const int mk = m8 >> 1;

#pragma unroll 1
    for (int s = 0; s < SP; s++) {
        int slot = s & 1;
        mbar_wait(smb + SM_MBAR + slot * 8, (s >> 1) & 1);

        uint32_t abase = smb + SM_A + slot * ASLOT;
        uint32_t wbase = smb + SM_W + slot * WSLOT;

#pragma unroll
        for (int ks = 0; ks < 4; ks++) {
            int unit = 2 * ks + mk;
            uint32_t aaddr = abase + rl * 2048 + t8 * 128 + ((unit ^ t8) << 4);
            uint32_t ah[4], al[4];
            ldsm4(aaddr,        ah[0], ah[1], ah[2], ah[3]);
            ldsm4(aaddr + 1024, al[0], al[1], al[2], al[3]);
            uint32_t bh0[4], bh1[4], bl0[4], bl1[4];
#pragma unroll
            for (int nb = 0; nb < 2; nb++) {
                int nrow = nb * 16 + (m8 & 1) * 8 + t8;
                uint32_t baddr = wbase + nrow * 128 + ((unit ^ (nrow & 7)) << 4);
                uint32_t* bh = nb ? bh1 : bh0;
                uint32_t* bl = nb ? bl1 : bl0;
                ldsm4(baddr,        bh[0], bh[1], bh[2], bh[3]);
                ldsm4(baddr + 4096, bl[0], bl[1], bl[2], bl[3]);
            }
            mma_bf16(acc[0], ah[0], ah[1], ah[2], ah[3], bh0[0], bh0[2]);
            mma_bf16(acc[1], ah[0], ah[1], ah[2], ah[3], bh0[1], bh0[3]);
            mma_bf16(acc[2], ah[0], ah[1], ah[2], ah[3], bh1[0], bh1[2]);
            mma_bf16(acc[3], ah[0], ah[1], ah[2], ah[3], bh1[1], bh1[3]);
            mma_bf16(acc[0], al[0], al[1], al[2], al[3], bh0[0], bh0[2]);
            mma_bf16(acc[1], al[0], al[1], al[2], al[3], bh0[1], bh0[3]);
            mma_bf16(acc[2], al[0], al[1], al[2], al[3], bh1[0], bh1[2]);
            mma_bf16(acc[3], al[0], al[1], al[2], al[3], bh1[1], bh1[3]);
            mma_bf16(acc[0], ah[0], ah[1], ah[2], ah[3], bl0[0], bl0[2]);
            mma_bf16(acc[1], ah[0], ah[1], ah[2], ah[3], bl0[1], bl0[3]);
            mma_bf16(acc[2], ah[0], ah[1], ah[2], ah[3], bl1[0], bl1[2]);
            mma_bf16(acc[3], ah[0], ah[1], ah[2], ah[3], bl1[1], bl1[3]);
        }

        __syncthreads();
        if (s + 2 < SP) gather(s + 2);
    }

    const int gr  = wid * 16 + (lane >> 2);
    const int col = (lane & 3) * 2;
    const int b0r = gr & 7;
    const int nr0 = n0 + (gr >> 3);
    const int nr1 = n0 + ((gr + 8) >> 3);
    float* po0 = out + ((size_t)b0r * NU + nr0) * CO;
    float* po1 = out + ((size_t)b0r * NU + nr1) * CO;
#pragma unroll
    for (int nt = 0; nt < 4; nt++) {
        int o = nt * 8 + col;
        float c0 = __ldg(bias + o), c1 = __ldg(bias + o + 1);
        float2 v0 = make_float2(fmaxf(acc[nt][0] + c0, 0.f), fmaxf(acc[nt][1] + c1, 0.f));
        float2 v1 = make_float2(fmaxf(acc[nt][2] + c0, 0.f), fmaxf(acc[nt][3] + c1, 0.f));
        *reinterpret_cast<float2*>(po0 + o) = v0;
        *reinterpret_cast<float2*>(po1 + o) = v1;
    }
}

// ---------------------------------------------------------------------------
// Launch (3 kernels)
// ---------------------------------------------------------------------------
extern "C" void kernel_launch(void* const* d_in, const int* in_sizes, int n_in,
                              void* d_out, int out_size) {
    const float* x        = (const float*)d_in[0];
    const int*   up_rows  = (const int*)  d_in[1];
    const int*   up_cols  = (const int*)  d_in[2];
    const float* up_vals  = (const float*)d_in[3];
    const int*   sidx     = (const int*)  d_in[4];
    const float* weight   = (const float*)d_in[5];
    const float* bias     = (const float*)d_in[6];
    float*       out      = (float*)d_out;

    ell_fill<<<(NNZE + 255) / 256, 256>>>(up_rows, up_cols, up_vals, weight);
    gather_pool<<<(NU * 16) / 256, 256>>>(x);

    cudaFuncSetAttribute(spiral_mma,
                         cudaFuncAttributeMaxDynamicSharedMemorySize, SM_TOT);
    spiral_mma<<<NU / 16, 256, SM_TOT>>>(sidx, bias, out);
}

// round 12
// speedup vs baseline: 3.5360x; 1.0928x over previous
#include <cuda_runtime.h>
#include <cuda_bf16.h>
#include <cstdint>

// Problem constants
#define BB   8
#define ND   12288
#define NU   49152
#define CI   64
#define CO   32
#define SP   9
#define NNZE 147456
#define KTOT (SP * CI)   // 576
#define ELLW 32          // padded entries per row (lambda=3; overflow P ~1e-21)

// ---------------------------------------------------------------------------
// Device scratch (statics zero-initialized; g_cnt re-zeroed by spiral_mma)
// ---------------------------------------------------------------------------
__device__ int   g_cnt[NU];
__device__ int   g_ellc[NU * ELLW];     // col per slot
__device__ float g_ellv[NU * ELLW];     // val per slot
// pooled: per row a 2KB chunk: [hi: b0..b7 x 128B | lo: b0..b7 x 128B],
// within (plane,b): 16B unit u stored at offset ((u ^ b) << 4)
__device__ __align__(256) unsigned char g_pool[(size_t)NU * 2048];
// weight, split bf16, [s][n=32][k=64] with 16B-unit XOR swizzle, ldmatrix-ready
__device__ __align__(256) unsigned short g_wh[SP * CO * CI];
__device__ __align__(256) unsigned short g_wl[SP * CO * CI];

// ---------------------------------------------------------------------------
// Launch 0: ELL build (hist+fill fused) + weight split/swizzle prepack
// ---------------------------------------------------------------------------
__global__ void ell_fill(const int*   __restrict__ rows,
                         const int*   __restrict__ cols,
                         const float* __restrict__ vals,
                         const float* __restrict__ weight) {
    int i = blockIdx.x * blockDim.x + threadIdx.x;
    if (i < NNZE) {
        int row = __ldg(rows + i);
        int p = atomicAdd(&g_cnt[row], 1);
        if (p < ELLW) {
            g_ellc[row * ELLW + p] = __ldg(cols + i);
            g_ellv[row * ELLW + p] = __ldg(vals + i);
        }
    }
    if (i < SP * CO * CI) {
        int k = i & 63;
        int n = (i >> 6) & 31;
        int s = i >> 11;
        float v = __ldg(weight + n * KTOT + s * CI + k);
        __nv_bfloat16 hi = __float2bfloat16(v);
        __nv_bfloat16 lo = __float2bfloat16(v - __bfloat162float(hi));
        int unit = k >> 3;
        int within = (k * 2) & 15;
        int byte = s * 4096 + n * 128 + ((unit ^ (n & 7)) << 4) + within;
        g_wh[byte >> 1] = __bfloat16_as_ushort(hi);
        g_wl[byte >> 1] = __bfloat16_as_ushort(lo);
    }
}

// ---------------------------------------------------------------------------
// Launch 1: gather-pool from ELL -> per-row 2KB chunks (hi/lo, batch-XOR)
// ---------------------------------------------------------------------------
__global__ void __launch_bounds__(256)
gather_pool(const float* __restrict__ x) {
    int gt  = blockIdx.x * blockDim.x + threadIdx.x;
    int row = gt >> 4;
    int c4  = gt & 15;
    if (row >= NU) return;

    int cnt = g_cnt[row];
    if (cnt > ELLW) cnt = ELLW;

    float4 acc[BB];
#pragma unroll
    for (int b = 0; b < BB; b++) acc[b] = make_float4(0.f, 0.f, 0.f, 0.f);

    const int*   ec = g_ellc + row * ELLW;
    const float* ev = g_ellv + row * ELLW;
    for (int i = 0; i < cnt; i++) {
        int   col = __ldg(ec + i);
        float v   = __ldg(ev + i);
        const float4* xp = reinterpret_cast<const float4*>(x) + (size_t)col * 16 + c4;
#pragma unroll
        for (int b = 0; b < BB; b++) {
            float4 xv = __ldg(xp + (size_t)b * (ND * 16));
            acc[b].x += v * xv.x; acc[b].y += v * xv.y;
            acc[b].z += v * xv.z; acc[b].w += v * xv.w;
        }
    }

    const int u = c4 >> 1;
    const int h = c4 & 1;
    unsigned char* chunk = g_pool + (size_t)row * 2048;
#pragma unroll
    for (int b = 0; b < BB; b++) {
        float f[4] = {acc[b].x, acc[b].y, acc[b].z, acc[b].w};
        ushort4 hh, ll;
        unsigned short* hp = &hh.x;
        unsigned short* lp = &ll.x;
#pragma unroll
        for (int j = 0; j < 4; j++) {
            __nv_bfloat16 hb = __float2bfloat16(f[j]);
            __nv_bfloat16 lb = __float2bfloat16(f[j] - __bfloat162float(hb));
            hp[j] = __bfloat16_as_ushort(hb);
            lp[j] = __bfloat16_as_ushort(lb);
        }
        int off = b * 128 + ((u ^ b) << 4) + h * 8;
        *reinterpret_cast<ushort4*>(chunk + off)        = hh;
        *reinterpret_cast<ushort4*>(chunk + 1024 + off) = ll;
    }
}

// ---------------------------------------------------------------------------
// Launch 2: fused spiral gather + mma.sync bf16-split GEMM + bias + relu.
// Block = 12 spiral rows x 8 batches = 96 GEMM rows x 32 outs, 6 warps.
// smem ~65KB -> 3 CTAs/SM (18 warps/SM, 3-way stage interleave).
// Also re-zeros g_cnt for the next call.
// ---------------------------------------------------------------------------
#define TROWS   12
#define ASLOT   (TROWS * 2048)              // 24576
#define WSLOT   8192
#define NTHR    (TROWS * 16)                // 192 threads, 6 warps
#define SM_MBAR 0
#define SM_SG   64                          // 108 ints
#define SM_A    1024
#define SM_W    (SM_A + 2 * ASLOT)          // 50176
#define SM_TOT  (SM_W + 2 * WSLOT)          // 66560 B

__device__ __forceinline__ uint32_t smem_u32(const void* p) {
    uint32_t a;
    asm("{ .reg .u64 t; cvta.to.shared.u64 t, %1; cvt.u32.u64 %0, t; }" : "=r"(a) : "l"(p));
    return a;
}
__device__ __forceinline__ void mbar_init(uint32_t m, uint32_t cnt) {
    asm volatile("mbarrier.init.shared.b64 [%0], %1;" :: "r"(m), "r"(cnt) : "memory");
}
__device__ __forceinline__ void mbar_expect_tx(uint32_t m, uint32_t bytes) {
    asm volatile("mbarrier.arrive.expect_tx.shared.b64 _, [%0], %1;"
                 :: "r"(m), "r"(bytes) : "memory");
}
__device__ __forceinline__ void mbar_wait(uint32_t m, uint32_t parity) {
    asm volatile(
        "{\n\t.reg .pred P;\n"
        "W_%=:\n\t"
        "mbarrier.try_wait.parity.shared::cta.b64 P, [%0], %1;\n\t"
        "@!P bra W_%=;\n\t}"
        :: "r"(m), "r"(parity) : "memory");
}
__device__ __forceinline__ void bulk_g2s(uint32_t dst, const void* src,
                                         uint32_t bytes, uint32_t mbar) {
    asm volatile(
        "cp.async.bulk.shared::cluster.global.mbarrier::complete_tx::bytes "
        "[%0], [%1], %2, [%3];"
        :: "r"(dst), "l"(src), "r"(bytes), "r"(mbar) : "memory");
}
__device__ __forceinline__ void ldsm4(uint32_t addr, uint32_t& r0, uint32_t& r1,
                                      uint32_t& r2, uint32_t& r3) {
    asm volatile("ldmatrix.sync.aligned.m8n8.x4.shared.b16 {%0,%1,%2,%3}, [%4];"
                 : "=r"(r0), "=r"(r1), "=r"(r2), "=r"(r3) : "r"(addr));
}
__device__ __forceinline__ void mma_bf16(float* c, uint32_t a0, uint32_t a1,
                                         uint32_t a2, uint32_t a3,
                                         uint32_t b0, uint32_t b1) {
    asm volatile(
        "mma.sync.aligned.m16n8k16.row.col.f32.bf16.bf16.f32 "
        "{%0,%1,%2,%3}, {%4,%5,%6,%7}, {%8,%9}, {%0,%1,%2,%3};"
        : "+f"(c[0]), "+f"(c[1]), "+f"(c[2]), "+f"(c[3])
        : "r"(a0), "r"(a1), "r"(a2), "r"(a3), "r"(b0), "r"(b1));
}

__global__ void __launch_bounds__(NTHR, 3)
spiral_mma(const int*   __restrict__ sidx,
           const float* __restrict__ bias,
           float*       __restrict__ out) {
    extern __shared__ char smraw[];
    uint32_t smb = smem_u32(smraw);

    const int tid  = threadIdx.x;
    const int wid  = tid >> 5;
    const int lane = tid & 31;
    const int n0   = blockIdx.x * TROWS;

    // Re-zero g_cnt for the next call (4096 blocks x 192 covers NU)
    {
        int i = blockIdx.x * NTHR + tid;
        if (i < NU) g_cnt[i] = 0;
    }

    int* Sg = reinterpret_cast<int*>(smraw + SM_SG);

    if (tid == 0) {
        mbar_init(smb + SM_MBAR + 0, 1);
        mbar_init(smb + SM_MBAR + 8, 1);
    }
    if (tid < TROWS * SP) Sg[tid] = __ldg(sidx + (size_t)n0 * SP + tid);
    __syncthreads();

    auto gather = [&](int s) {
        int slot = s & 1;
        uint32_t mbar = smb + SM_MBAR + slot * 8;
        if (tid == 0) mbar_expect_tx(mbar, ASLOT + WSLOT);
        if (tid < TROWS) {
            int idx = Sg[tid * SP + s];
            bulk_g2s(smb + SM_A + slot * ASLOT + tid * 2048,
                     g_pool + (size_t)idx * 2048, 2048, mbar);
        } else if (tid == TROWS) {
            bulk_g2s(smb + SM_W + slot * WSLOT,
                     reinterpret_cast<const char*>(g_wh) + s * 4096, 4096, mbar);
        } else if (tid == TROWS + 1) {
            bulk_g2s(smb + SM_W + slot * WSLOT + 4096,
                     reinterpret_cast<const char*>(g_wl) + s * 4096, 4096, mbar);
        }
    };

    gather(0);
    gather(1);

    float acc[4][4];
#pragma unroll
    for (int i = 0; i < 4; i++)
#pragma unroll
        for (int j = 0; j < 4; j++) acc[i][j] = 0.f;

    const int m8 = lane >> 3;
    const int t8 = lane & 7;
    const int rl = 2 * wid + (m8 & 1);     // local spiral row 0..11
    const int mk = m8 >> 1;

#pragma unroll 1
    for (int s = 0; s < SP; s++) {
        int slot = s & 1;
        mbar_wait(smb + SM_MBAR + slot * 8, (s >> 1) & 1);

        uint32_t abase = smb + SM_A + slot * ASLOT;
        uint32_t wbase = smb + SM_W + slot * WSLOT;

#pragma unroll
        for (int ks = 0; ks < 4; ks++) {
            int unit = 2 * ks + mk;
            uint32_t aaddr = abase + rl * 2048 + t8 * 128 + ((unit ^ t8) << 4);
            uint32_t ah[4], al[4];
            ldsm4(aaddr,        ah[0], ah[1], ah[2], ah[3]);
            ldsm4(aaddr + 1024, al[0], al[1], al[2], al[3]);
            uint32_t bh0[4], bh1[4], bl0[4], bl1[4];
#pragma unroll
            for (int nb = 0; nb < 2; nb++) {
                int nrow = nb * 16 + (m8 & 1) * 8 + t8;
                uint32_t baddr = wbase + nrow * 128 + ((unit ^ (nrow & 7)) << 4);
                uint32_t* bh = nb ? bh1 : bh0;
                uint32_t* bl = nb ? bl1 : bl0;
                ldsm4(baddr,        bh[0], bh[1], bh[2], bh[3]);
                ldsm4(baddr + 4096, bl[0], bl[1], bl[2], bl[3]);
            }
            mma_bf16(acc[0], ah[0], ah[1], ah[2], ah[3], bh0[0], bh0[2]);
            mma_bf16(acc[1], ah[0], ah[1], ah[2], ah[3], bh0[1], bh0[3]);
            mma_bf16(acc[2], ah[0], ah[1], ah[2], ah[3], bh1[0], bh1[2]);
            mma_bf16(acc[3], ah[0], ah[1], ah[2], ah[3], bh1[1], bh1[3]);
            mma_bf16(acc[0], al[0], al[1], al[2], al[3], bh0[0], bh0[2]);
            mma_bf16(acc[1], al[0], al[1], al[2], al[3], bh0[1], bh0[3]);
            mma_bf16(acc[2], al[0], al[1], al[2], al[3], bh1[0], bh1[2]);
            mma_bf16(acc[3], al[0], al[1], al[2], al[3], bh1[1], bh1[3]);
            mma_bf16(acc[0], ah[0], ah[1], ah[2], ah[3], bl0[0], bl0[2]);
            mma_bf16(acc[1], ah[0], ah[1], ah[2], ah[3], bl0[1], bl0[3]);
            mma_bf16(acc[2], ah[0], ah[1], ah[2], ah[3], bl1[0], bl1[2]);
            mma_bf16(acc[3], ah[0], ah[1], ah[2], ah[3], bl1[1], bl1[3]);
        }

        __syncthreads();
        if (s + 2 < SP) gather(s + 2);
    }

    // Epilogue: GEMM row g = wid*16 + (lane>>2) (+8): rl = g>>3, batch = g&7
    const int gr  = wid * 16 + (lane >> 2);
    const int col = (lane & 3) * 2;
    const int b0r = gr & 7;
    const int nr0 = n0 + (gr >> 3);
    const int nr1 = n0 + ((gr + 8) >> 3);
    float* po0 = out + ((size_t)b0r * NU + nr0) * CO;
    float* po1 = out + ((size_t)b0r * NU + nr1) * CO;
#pragma unroll
    for (int nt = 0; nt < 4; nt++) {
        int o = nt * 8 + col;
        float c0 = __ldg(bias + o), c1 = __ldg(bias + o + 1);
        float2 v0 = make_float2(fmaxf(acc[nt][0] + c0, 0.f), fmaxf(acc[nt][1] + c1, 0.f));
        float2 v1 = make_float2(fmaxf(acc[nt][2] + c0, 0.f), fmaxf(acc[nt][3] + c1, 0.f));
        *reinterpret_cast<float2*>(po0 + o) = v0;
        *reinterpret_cast<float2*>(po1 + o) = v1;
    }
}

// ---------------------------------------------------------------------------
// Launch (3 kernels)
// ---------------------------------------------------------------------------
extern "C" void kernel_launch(void* const* d_in, const int* in_sizes, int n_in,
                              void* d_out, int out_size) {
    const float* x        = (const float*)d_in[0];
    const int*   up_rows  = (const int*)  d_in[1];
    const int*   up_cols  = (const int*)  d_in[2];
    const float* up_vals  = (const float*)d_in[3];
    const int*   sidx     = (const int*)  d_in[4];
    const float* weight   = (const float*)d_in[5];
    const float* bias     = (const float*)d_in[6];
    float*       out      = (float*)d_out;

    ell_fill<<<(NNZE + 255) / 256, 256>>>(up_rows, up_cols, up_vals, weight);
    gather_pool<<<(NU * 16) / 256, 256>>>(x);

    cudaFuncSetAttribute(spiral_mma,
                         cudaFuncAttributeMaxDynamicSharedMemorySize, SM_TOT);
    spiral_mma<<<NU / TROWS, NTHR, SM_TOT>>>(sidx, bias, out);
}

// round 13
// speedup vs baseline: 4.9666x; 1.4046x over previous
#include <cuda_runtime.h>
#include <cuda_fp16.h>
#include <cstdint>

// Problem constants
#define BB   8
#define ND   12288
#define NU   49152
#define CI   64
#define CO   32
#define SP   9
#define NNZE 147456
#define KTOT (SP * CI)   // 576
#define ELLW 32          // padded entries per row (lambda=3; overflow P ~1e-21)

// ---------------------------------------------------------------------------
// Device scratch (statics zero-initialized; g_cnt re-zeroed by spiral_mma)
// ---------------------------------------------------------------------------
__device__ int   g_cnt[NU];
__device__ int   g_ellc[NU * ELLW];     // col per slot
__device__ float g_ellv[NU * ELLW];     // val per slot
// pooled: per row a 1KB chunk: b0..b7 x 128B (fp16, 64 ch);
// within batch b: 16B unit u stored at offset ((u ^ b) << 4)
__device__ __align__(256) unsigned char g_pool[(size_t)NU * 1024];
// weight, split fp16 hi/lo, [s][n=32][k=64] with 16B-unit XOR swizzle
__device__ __align__(256) unsigned short g_wh[SP * CO * CI];
__device__ __align__(256) unsigned short g_wl[SP * CO * CI];

// ---------------------------------------------------------------------------
// Launch 0: ELL build (hist+fill fused) + weight fp16-split/swizzle prepack
// ---------------------------------------------------------------------------
__global__ void ell_fill(const int*   __restrict__ rows,
                         const int*   __restrict__ cols,
                         const float* __restrict__ vals,
                         const float* __restrict__ weight) {
    int i = blockIdx.x * blockDim.x + threadIdx.x;
    if (i < NNZE) {
        int row = __ldg(rows + i);
        int p = atomicAdd(&g_cnt[row], 1);
        if (p < ELLW) {
            g_ellc[row * ELLW + p] = __ldg(cols + i);
            g_ellv[row * ELLW + p] = __ldg(vals + i);
        }
    }
    if (i < SP * CO * CI) {
        int k = i & 63;
        int n = (i >> 6) & 31;
        int s = i >> 11;
        float v = __ldg(weight + n * KTOT + s * CI + k);
        __half hi = __float2half_rn(v);
        __half lo = __float2half_rn(v - __half2float(hi));
        int unit = k >> 3;
        int within = (k * 2) & 15;
        int byte = s * 4096 + n * 128 + ((unit ^ (n & 7)) << 4) + within;
        g_wh[byte >> 1] = __half_as_ushort(hi);
        g_wl[byte >> 1] = __half_as_ushort(lo);
    }
}

// ---------------------------------------------------------------------------
// Launch 1: gather-pool from ELL -> per-row 1KB fp16 chunks (batch-XOR units)
// thread = (row, c4)
// ---------------------------------------------------------------------------
__global__ void __launch_bounds__(256)
gather_pool(const float* __restrict__ x) {
    int gt  = blockIdx.x * blockDim.x + threadIdx.x;
    int row = gt >> 4;
    int c4  = gt & 15;
    if (row >= NU) return;

    int cnt = g_cnt[row];
    if (cnt > ELLW) cnt = ELLW;

    float4 acc[BB];
#pragma unroll
    for (int b = 0; b < BB; b++) acc[b] = make_float4(0.f, 0.f, 0.f, 0.f);

    const int*   ec = g_ellc + row * ELLW;
    const float* ev = g_ellv + row * ELLW;
    for (int i = 0; i < cnt; i++) {
        int   col = __ldg(ec + i);
        float v   = __ldg(ev + i);
        const float4* xp = reinterpret_cast<const float4*>(x) + (size_t)col * 16 + c4;
#pragma unroll
        for (int b = 0; b < BB; b++) {
            float4 xv = __ldg(xp + (size_t)b * (ND * 16));
            acc[b].x += v * xv.x; acc[b].y += v * xv.y;
            acc[b].z += v * xv.z; acc[b].w += v * xv.w;
        }
    }

    const int u = c4 >> 1;
    const int h = c4 & 1;
    unsigned char* chunk = g_pool + (size_t)row * 1024;
#pragma unroll
    for (int b = 0; b < BB; b++) {
        ushort4 hh;
        hh.x = __half_as_ushort(__float2half_rn(acc[b].x));
        hh.y = __half_as_ushort(__float2half_rn(acc[b].y));
        hh.z = __half_as_ushort(__float2half_rn(acc[b].z));
        hh.w = __half_as_ushort(__float2half_rn(acc[b].w));
        int off = b * 128 + ((u ^ b) << 4) + h * 8;
        *reinterpret_cast<ushort4*>(chunk + off) = hh;
    }
}

// ---------------------------------------------------------------------------
// Launch 2: fused spiral gather + mma.sync fp16 (2-term W split) + bias+relu.
// Block = 12 spiral rows x 8 batches = 96 GEMM rows x 32 outs, 6 warps.
// smem ~41.5KB -> 5 CTAs/SM (30 warps/SM, 5-way stage interleave).
// Also re-zeros g_cnt for the next call.
// ---------------------------------------------------------------------------
#define TROWS   12
#define ASLOT   (TROWS * 1024)              // 12288
#define WSLOT   8192
#define NTHR    (TROWS * 16)                // 192 threads, 6 warps
#define SM_MBAR 0
#define SM_SG   64                          // 108 ints
#define SM_A    1024
#define SM_W    (SM_A + 2 * ASLOT)          // 25600
#define SM_TOT  (SM_W + 2 * WSLOT)          // 41984 B

__device__ __forceinline__ uint32_t smem_u32(const void* p) {
    uint32_t a;
    asm("{ .reg .u64 t; cvta.to.shared.u64 t, %1; cvt.u32.u64 %0, t; }" : "=r"(a) : "l"(p));
    return a;
}
__device__ __forceinline__ void mbar_init(uint32_t m, uint32_t cnt) {
    asm volatile("mbarrier.init.shared.b64 [%0], %1;" :: "r"(m), "r"(cnt) : "memory");
}
__device__ __forceinline__ void mbar_expect_tx(uint32_t m, uint32_t bytes) {
    asm volatile("mbarrier.arrive.expect_tx.shared.b64 _, [%0], %1;"
                 :: "r"(m), "r"(bytes) : "memory");
}
__device__ __forceinline__ void mbar_wait(uint32_t m, uint32_t parity) {
    asm volatile(
        "{\n\t.reg .pred P;\n"
        "W_%=:\n\t"
        "mbarrier.try_wait.parity.shared::cta.b64 P, [%0], %1;\n\t"
        "@!P bra W_%=;\n\t}"
        :: "r"(m), "r"(parity) : "memory");
}
__device__ __forceinline__ void bulk_g2s(uint32_t dst, const void* src,
                                         uint32_t bytes, uint32_t mbar) {
    asm volatile(
        "cp.async.bulk.shared::cluster.global.mbarrier::complete_tx::bytes "
        "[%0], [%1], %2, [%3];"
        :: "r"(dst), "l"(src), "r"(bytes), "r"(mbar) : "memory");
}
__device__ __forceinline__ void ldsm4(uint32_t addr, uint32_t& r0, uint32_t& r1,
                                      uint32_t& r2, uint32_t& r3) {
    asm volatile("ldmatrix.sync.aligned.m8n8.x4.shared.b16 {%0,%1,%2,%3}, [%4];"
                 : "=r"(r0), "=r"(r1), "=r"(r2), "=r"(r3) : "r"(addr));
}
__device__ __forceinline__ void mma_f16(float* c, uint32_t a0, uint32_t a1,
                                        uint32_t a2, uint32_t a3,
                                        uint32_t b0, uint32_t b1) {
    asm volatile(
        "mma.sync.aligned.m16n8k16.row.col.f32.f16.f16.f32 "
        "{%0,%1,%2,%3}, {%4,%5,%6,%7}, {%8,%9}, {%0,%1,%2,%3};"
        : "+f"(c[0]), "+f"(c[1]), "+f"(c[2]), "+f"(c[3])
        : "r"(a0), "r"(a1), "r"(a2), "r"(a3), "r"(b0), "r"(b1));
}

__global__ void __launch_bounds__(NTHR, 5)
spiral_mma(const int*   __restrict__ sidx,
           const float* __restrict__ bias,
           float*       __restrict__ out) {
    extern __shared__ char smraw[];
    uint32_t smb = smem_u32(smraw);

    const int tid  = threadIdx.x;
    const int wid  = tid >> 5;
    const int lane = tid & 31;
    const int n0   = blockIdx.x * TROWS;

    // Re-zero g_cnt for the next call (4096 blocks x 192 covers NU)
    {
        int i = blockIdx.x * NTHR + tid;
        if (i < NU) g_cnt[i] = 0;
    }

    int* Sg = reinterpret_cast<int*>(smraw + SM_SG);

    if (tid == 0) {
        mbar_init(smb + SM_MBAR + 0, 1);
        mbar_init(smb + SM_MBAR + 8, 1);
    }
    if (tid < TROWS * SP) Sg[tid] = __ldg(sidx + (size_t)n0 * SP + tid);
    __syncthreads();

    auto gather = [&](int s) {
        int slot = s & 1;
        uint32_t mbar = smb + SM_MBAR + slot * 8;
        if (tid == 0) mbar_expect_tx(mbar, ASLOT + WSLOT);
        if (tid < TROWS) {
            int idx = Sg[tid * SP + s];
            bulk_g2s(smb + SM_A + slot * ASLOT + tid * 1024,
                     g_pool + (size_t)idx * 1024, 1024, mbar);
        } else if (tid == TROWS) {
            bulk_g2s(smb + SM_W + slot * WSLOT,
                     reinterpret_cast<const char*>(g_wh) + s * 4096, 4096, mbar);
        } else if (tid == TROWS + 1) {
            bulk_g2s(smb + SM_W + slot * WSLOT + 4096,
                     reinterpret_cast<const char*>(g_wl) + s * 4096, 4096, mbar);
        }
    };

    gather(0);
    gather(1);

    float acc[4][4];
#pragma unroll
    for (int i = 0; i < 4; i++)
#pragma unroll
        for (int j = 0; j < 4; j++) acc[i][j] = 0.f;

    const int m8 = lane >> 3;
    const int t8 = lane & 7;
    const int rl = 2 * wid + (m8 & 1);     // local spiral row 0..11
    const int mk = m8 >> 1;

#pragma unroll 1
    for (int s = 0; s < SP; s++) {
        int slot = s & 1;
        mbar_wait(smb + SM_MBAR + slot * 8, (s >> 1) & 1);

        uint32_t abase = smb + SM_A + slot * ASLOT;
        uint32_t wbase = smb + SM_W + slot * WSLOT;

#pragma unroll
        for (int ks = 0; ks < 4; ks++) {
            int unit = 2 * ks + mk;
            uint32_t aaddr = abase + rl * 1024 + t8 * 128 + ((unit ^ t8) << 4);
            uint32_t ah[4];
            ldsm4(aaddr, ah[0], ah[1], ah[2], ah[3]);
            uint32_t bh0[4], bh1[4], bl0[4], bl1[4];
#pragma unroll
            for (int nb = 0; nb < 2; nb++) {
                int nrow = nb * 16 + (m8 & 1) * 8 + t8;
                uint32_t baddr = wbase + nrow * 128 + ((unit ^ (nrow & 7)) << 4);
                uint32_t* bh = nb ? bh1 : bh0;
                uint32_t* bl = nb ? bl1 : bl0;
                ldsm4(baddr,        bh[0], bh[1], bh[2], bh[3]);
                ldsm4(baddr + 4096, bl[0], bl[1], bl[2], bl[3]);
            }
            mma_f16(acc[0], ah[0], ah[1], ah[2], ah[3], bh0[0], bh0[2]);
            mma_f16(acc[1], ah[0], ah[1], ah[2], ah[3], bh0[1], bh0[3]);
            mma_f16(acc[2], ah[0], ah[1], ah[2], ah[3], bh1[0], bh1[2]);
            mma_f16(acc[3], ah[0], ah[1], ah[2], ah[3], bh1[1], bh1[3]);
            mma_f16(acc[0], ah[0], ah[1], ah[2], ah[3], bl0[0], bl0[2]);
            mma_f16(acc[1], ah[0], ah[1], ah[2], ah[3], bl0[1], bl0[3]);
            mma_f16(acc[2], ah[0], ah[1], ah[2], ah[3], bl1[0], bl1[2]);
            mma_f16(acc[3], ah[0], ah[1], ah[2], ah[3], bl1[1], bl1[3]);
        }

        __syncthreads();
        if (s + 2 < SP) gather(s + 2);
    }

    // Epilogue: GEMM row g = wid*16 + (lane>>2) (+8): rl = g>>3, batch = g&7
    const int gr  = wid * 16 + (lane >> 2);
    const int col = (lane & 3) * 2;
    const int b0r = gr & 7;
    const int nr0 = n0 + (gr >> 3);
    const int nr1 = n0 + ((gr + 8) >> 3);
    float* po0 = out + ((size_t)b0r * NU + nr0) * CO;
    float* po1 = out + ((size_t)b0r * NU + nr1) * CO;
#pragma unroll
    for (int nt = 0; nt < 4; nt++) {
        int o = nt * 8 + col;
        float c0 = __ldg(bias + o), c1 = __ldg(bias + o + 1);
        float2 v0 = make_float2(fmaxf(acc[nt][0] + c0, 0.f), fmaxf(acc[nt][1] + c1, 0.f));
        float2 v1 = make_float2(fmaxf(acc[nt][2] + c0, 0.f), fmaxf(acc[nt][3] + c1, 0.f));
        *reinterpret_cast<float2*>(po0 + o) = v0;
        *reinterpret_cast<float2*>(po1 + o) = v1;
    }
}

// ---------------------------------------------------------------------------
// Launch (3 kernels)
// ---------------------------------------------------------------------------
extern "C" void kernel_launch(void* const* d_in, const int* in_sizes, int n_in,
                              void* d_out, int out_size) {
    const float* x        = (const float*)d_in[0];
    const int*   up_rows  = (const int*)  d_in[1];
    const int*   up_cols  = (const int*)  d_in[2];
    const float* up_vals  = (const float*)d_in[3];
    const int*   sidx     = (const int*)  d_in[4];
    const float* weight   = (const float*)d_in[5];
    const float* bias     = (const float*)d_in[6];
    float*       out      = (float*)d_out;

    ell_fill<<<(NNZE + 255) / 256, 256>>>(up_rows, up_cols, up_vals, weight);
    gather_pool<<<(NU * 16) / 256, 256>>>(x);

    cudaFuncSetAttribute(spiral_mma,
                         cudaFuncAttributeMaxDynamicSharedMemorySize, SM_TOT);
    spiral_mma<<<NU / TROWS, NTHR, SM_TOT>>>(sidx, bias, out);
}

// round 15
// speedup vs baseline: 5.9375x; 1.1955x over previous
#include <cuda_runtime.h>
#include <cuda_fp16.h>
#include <cstdint>

// Problem constants
#define BB   8
#define ND   12288
#define NU   49152
#define CI   64
#define CO   32
#define SP   9
#define NNZE 147456
#define KTOT (SP * CI)   // 576
#define ELLW 32          // padded entries per row (lambda=3; overflow P ~1e-21)

// half2 bit-cast helpers (defined BEFORE any use)
__device__ __forceinline__ __half2 u2h2(unsigned int u) {
    __half2 h;
    *reinterpret_cast<unsigned int*>(&h) = u;
    return h;
}
__device__ __forceinline__ unsigned int h22u(__half2 h) {
    return *reinterpret_cast<unsigned int*>(&h);
}

// ---------------------------------------------------------------------------
// Device scratch (statics zero-initialized; g_cnt re-zeroed by spiral_mma)
// ---------------------------------------------------------------------------
__device__ int   g_cnt[NU];
__device__ int   g_ellc[NU * ELLW];     // col per slot
__device__ float g_ellv[NU * ELLW];     // val per slot
// x converted to fp16: [b][col][64ch]
__device__ __align__(256) unsigned short g_xh[(size_t)BB * ND * CI];
// pooled: per row a 1KB chunk: b0..b7 x 128B (fp16, 64 ch);
// within batch b: 16B unit u stored at offset ((u ^ b) << 4)
__device__ __align__(256) unsigned char g_pool[(size_t)NU * 1024];
// weight fp16, [s][n=32][k=64] with 16B-unit XOR swizzle, ldmatrix-ready
__device__ __align__(256) unsigned short g_wh[SP * CO * CI];

// ---------------------------------------------------------------------------
// Launch 0: ELL build + weight fp16/swizzle prepack + x -> fp16 conversion
// ---------------------------------------------------------------------------
__global__ void ell_fill(const int*   __restrict__ rows,
                         const int*   __restrict__ cols,
                         const float* __restrict__ vals,
                         const float* __restrict__ weight,
                         const float* __restrict__ x) {
    int i = blockIdx.x * blockDim.x + threadIdx.x;
    if (i < NNZE) {
        int row = __ldg(rows + i);
        int p = atomicAdd(&g_cnt[row], 1);
        if (p < ELLW) {
            g_ellc[row * ELLW + p] = __ldg(cols + i);
            g_ellv[row * ELLW + p] = __ldg(vals + i);
        }
    }
    if (i < SP * CO * CI) {
        int k = i & 63;
        int n = (i >> 6) & 31;
        int s = i >> 11;
        float v = __ldg(weight + n * KTOT + s * CI + k);
        int unit = k >> 3;
        int within = (k * 2) & 15;
        int byte = s * 4096 + n * 128 + ((unit ^ (n & 7)) << 4) + within;
        g_wh[byte >> 1] = __half_as_ushort(__float2half_rn(v));
    }
    // x -> fp16, 8 floats per chunk, grid-stride
    const int total = NNZE;           // grid*block
    uint4* dst = reinterpret_cast<uint4*>(g_xh);
    for (int j = i; j < (BB * ND * CI) / 8; j += total) {
        const float4* s = reinterpret_cast<const float4*>(x) + (size_t)j * 2;
        float4 a = __ldg(s), b = __ldg(s + 1);
        uint4 o;
        o.x = h22u(__floats2half2_rn(a.x, a.y));
        o.y = h22u(__floats2half2_rn(a.z, a.w));
        o.z = h22u(__floats2half2_rn(b.x, b.y));
        o.w = h22u(__floats2half2_rn(b.z, b.w));
        dst[j] = o;
    }
}

// ---------------------------------------------------------------------------
// Launch 1: gather-pool from ELL (fp16 x) -> per-row 1KB fp16 chunks
// thread = (row, c4)
// ---------------------------------------------------------------------------
__global__ void __launch_bounds__(256)
gather_pool() {
    int gt  = blockIdx.x * blockDim.x + threadIdx.x;
    int row = gt >> 4;
    int c4  = gt & 15;
    if (row >= NU) return;

    int cnt = g_cnt[row];
    if (cnt > ELLW) cnt = ELLW;

    float4 acc[BB];
#pragma unroll
    for (int b = 0; b < BB; b++) acc[b] = make_float4(0.f, 0.f, 0.f, 0.f);

    const int*   ec = g_ellc + row * ELLW;
    const float* ev = g_ellv + row * ELLW;
    for (int i = 0; i < cnt; i++) {
        int   col = __ldg(ec + i);
        float v   = __ldg(ev + i);
        const uint2* xp = reinterpret_cast<const uint2*>(g_xh)
                        + ((size_t)col * 16 + c4);
#pragma unroll
        for (int b = 0; b < BB; b++) {
            uint2 xv = __ldg(xp + (size_t)b * (ND * 16));
            float2 f0 = __half22float2(u2h2(xv.x));
            float2 f1 = __half22float2(u2h2(xv.y));
            acc[b].x += v * f0.x; acc[b].y += v * f0.y;
            acc[b].z += v * f1.x; acc[b].w += v * f1.y;
        }
    }

    const int u = c4 >> 1;
    const int h = c4 & 1;
    unsigned char* chunk = g_pool + (size_t)row * 1024;
#pragma unroll
    for (int b = 0; b < BB; b++) {
        ushort4 hh;
        hh.x = __half_as_ushort(__float2half_rn(acc[b].x));
        hh.y = __half_as_ushort(__float2half_rn(acc[b].y));
        hh.z = __half_as_ushort(__float2half_rn(acc[b].z));
        hh.w = __half_as_ushort(__float2half_rn(acc[b].w));
        int off = b * 128 + ((u ^ b) << 4) + h * 8;
        *reinterpret_cast<ushort4*>(chunk + off) = hh;
    }
}

// ---------------------------------------------------------------------------
// Launch 2: fused spiral gather + mma.sync fp16 GEMM + bias + relu.
// Block = 12 spiral rows x 8 batches = 96 GEMM rows x 32 outs, 6 warps.
// smem ~33.8KB -> 6 CTAs/SM. Also re-zeros g_cnt for the next call.
// ---------------------------------------------------------------------------
#define TROWS   12
#define ASLOT   (TROWS * 1024)              // 12288
#define WSLOT   4096
#define NTHR    (TROWS * 16)                // 192 threads, 6 warps
#define SM_MBAR 0
#define SM_SG   64                          // 108 ints
#define SM_A    1024
#define SM_W    (SM_A + 2 * ASLOT)          // 25600
#define SM_TOT  (SM_W + 2 * WSLOT)          // 33792 B

__device__ __forceinline__ uint32_t smem_u32(const void* p) {
    uint32_t a;
    asm("{ .reg .u64 t; cvta.to.shared.u64 t, %1; cvt.u32.u64 %0, t; }" : "=r"(a) : "l"(p));
    return a;
}
__device__ __forceinline__ void mbar_init(uint32_t m, uint32_t cnt) {
    asm volatile("mbarrier.init.shared.b64 [%0], %1;" :: "r"(m), "r"(cnt) : "memory");
}
__device__ __forceinline__ void mbar_expect_tx(uint32_t m, uint32_t bytes) {
    asm volatile("mbarrier.arrive.expect_tx.shared.b64 _, [%0], %1;"
                 :: "r"(m), "r"(bytes) : "memory");
}
__device__ __forceinline__ void mbar_wait(uint32_t m, uint32_t parity) {
    asm volatile(
        "{\n\t.reg .pred P;\n"
        "W_%=:\n\t"
        "mbarrier.try_wait.parity.shared::cta.b64 P, [%0], %1;\n\t"
        "@!P bra W_%=;\n\t}"
        :: "r"(m), "r"(parity) : "memory");
}
__device__ __forceinline__ void bulk_g2s(uint32_t dst, const void* src,
                                         uint32_t bytes, uint32_t mbar) {
    asm volatile(
        "cp.async.bulk.shared::cluster.global.mbarrier::complete_tx::bytes "
        "[%0], [%1], %2, [%3];"
        :: "r"(dst), "l"(src), "r"(bytes), "r"(mbar) : "memory");
}
__device__ __forceinline__ void ldsm4(uint32_t addr, uint32_t& r0, uint32_t& r1,
                                      uint32_t& r2, uint32_t& r3) {
    asm volatile("ldmatrix.sync.aligned.m8n8.x4.shared.b16 {%0,%1,%2,%3}, [%4];"
                 : "=r"(r0), "=r"(r1), "=r"(r2), "=r"(r3) : "r"(addr));
}
__device__ __forceinline__ void mma_f16(float* c, uint32_t a0, uint32_t a1,
                                        uint32_t a2, uint32_t a3,
                                        uint32_t b0, uint32_t b1) {
    asm volatile(
        "mma.sync.aligned.m16n8k16.row.col.f32.f16.f16.f32 "
        "{%0,%1,%2,%3}, {%4,%5,%6,%7}, {%8,%9}, {%0,%1,%2,%3};"
        : "+f"(c[0]), "+f"(c[1]), "+f"(c[2]), "+f"(c[3])
        : "r"(a0), "r"(a1), "r"(a2), "r"(a3), "r"(b0), "r"(b1));
}

__global__ void __launch_bounds__(NTHR, 6)
spiral_mma(const int*   __restrict__ sidx,
           const float* __restrict__ bias,
           float*       __restrict__ out) {
    extern __shared__ char smraw[];
    uint32_t smb = smem_u32(smraw);

    const int tid  = threadIdx.x;
    const int wid  = tid >> 5;
    const int lane = tid & 31;
    const int n0   = blockIdx.x * TROWS;

    // Re-zero g_cnt for the next call (4096 blocks x 192 covers NU)
    {
        int i = blockIdx.x * NTHR + tid;
        if (i < NU) g_cnt[i] = 0;
    }

    int* Sg = reinterpret_cast<int*>(smraw + SM_SG);

    if (tid == 0) {
        mbar_init(smb + SM_MBAR + 0, 1);
        mbar_init(smb + SM_MBAR + 8, 1);
    }
    if (tid < TROWS * SP) Sg[tid] = __ldg(sidx + (size_t)n0 * SP + tid);
    __syncthreads();

    auto gather = [&](int s) {
        int slot = s & 1;
        uint32_t mbar = smb + SM_MBAR + slot * 8;
        if (tid == 0) mbar_expect_tx(mbar, ASLOT + WSLOT);
        if (tid < TROWS) {
            int idx = Sg[tid * SP + s];
            bulk_g2s(smb + SM_A + slot * ASLOT + tid * 1024,
                     g_pool + (size_t)idx * 1024, 1024, mbar);
        } else if (tid == TROWS) {
            bulk_g2s(smb + SM_W + slot * WSLOT,
                     reinterpret_cast<const char*>(g_wh) + s * 4096, 4096, mbar);
        }
    };

    gather(0);
    gather(1);

    float acc[4][4];
#pragma unroll
    for (int i = 0; i < 4; i++)
#pragma unroll
        for (int j = 0; j < 4; j++) acc[i][j] = 0.f;

    const int m8 = lane >> 3;
    const int t8 = lane & 7;
    const int rl = 2 * wid + (m8 & 1);     // local spiral row 0..11
    const int mk = m8 >> 1;

#pragma unroll 1
    for (int s = 0; s < SP; s++) {
        int slot = s & 1;
        mbar_wait(smb + SM_MBAR + slot * 8, (s >> 1) & 1);

        uint32_t abase = smb + SM_A + slot * ASLOT;
        uint32_t wbase = smb + SM_W + slot * WSLOT;

#pragma unroll
        for (int ks = 0; ks < 4; ks++) {
            int unit = 2 * ks + mk;
            uint32_t aaddr = abase + rl * 1024 + t8 * 128 + ((unit ^ t8) << 4);
            uint32_t ah[4];
            ldsm4(aaddr, ah[0], ah[1], ah[2], ah[3]);
            uint32_t bh0[4], bh1[4];
#pragma unroll
            for (int nb = 0; nb < 2; nb++) {
                int nrow = nb * 16 + (m8 & 1) * 8 + t8;
                uint32_t baddr = wbase + nrow * 128 + ((unit ^ (nrow & 7)) << 4);
                uint32_t* bh = nb ? bh1 : bh0;
                ldsm4(baddr, bh[0], bh[1], bh[2], bh[3]);
            }
            mma_f16(acc[0], ah[0], ah[1], ah[2], ah[3], bh0[0], bh0[2]);
            mma_f16(acc[1], ah[0], ah[1], ah[2], ah[3], bh0[1], bh0[3]);
            mma_f16(acc[2], ah[0], ah[1], ah[2], ah[3], bh1[0], bh1[2]);
            mma_f16(acc[3], ah[0], ah[1], ah[2], ah[3], bh1[1], bh1[3]);
        }

        __syncthreads();
        if (s + 2 < SP) gather(s + 2);
    }

    // Epilogue: GEMM row g = wid*16 + (lane>>2) (+8): rl = g>>3, batch = g&7
    const int gr  = wid * 16 + (lane >> 2);
    const int col = (lane & 3) * 2;
    const int b0r = gr & 7;
    const int nr0 = n0 + (gr >> 3);
    const int nr1 = n0 + ((gr + 8) >> 3);
    float* po0 = out + ((size_t)b0r * NU + nr0) * CO;
    float* po1 = out + ((size_t)b0r * NU + nr1) * CO;
#pragma unroll
    for (int nt = 0; nt < 4; nt++) {
        int o = nt * 8 + col;
        float c0 = __ldg(bias + o), c1 = __ldg(bias + o + 1);
        float2 v0 = make_float2(fmaxf(acc[nt][0] + c0, 0.f), fmaxf(acc[nt][1] + c1, 0.f));
        float2 v1 = make_float2(fmaxf(acc[nt][2] + c0, 0.f), fmaxf(acc[nt][3] + c1, 0.f));
        *reinterpret_cast<float2*>(po0 + o) = v0;
        *reinterpret_cast<float2*>(po1 + o) = v1;
    }
}

// ---------------------------------------------------------------------------
// Launch (3 kernels)
// ---------------------------------------------------------------------------
extern "C" void kernel_launch(void* const* d_in, const int* in_sizes, int n_in,
                              void* d_out, int out_size) {
    const float* x        = (const float*)d_in[0];
    const int*   up_rows  = (const int*)  d_in[1];
    const int*   up_cols  = (const int*)  d_in[2];
    const float* up_vals  = (const float*)d_in[3];
    const int*   sidx     = (const int*)  d_in[4];
    const float* weight   = (const float*)d_in[5];
    const float* bias     = (const float*)d_in[6];
    float*       out      = (float*)d_out;

    ell_fill<<<(NNZE + 255) / 256, 256>>>(up_rows, up_cols, up_vals, weight, x);
    gather_pool<<<(NU * 16) / 256, 256>>>();

    cudaFuncSetAttribute(spiral_mma,
                         cudaFuncAttributeMaxDynamicSharedMemorySize, SM_TOT);
    spiral_mma<<<NU / TROWS, NTHR, SM_TOT>>>(sidx, bias, out);
}

// round 16
// speedup vs baseline: 6.1748x; 1.0400x over previous
#include <cuda_runtime.h>
#include <cuda_fp16.h>
#include <cstdint>

// Problem constants
#define BB   8
#define ND   12288
#define NU   49152
#define CI   64
#define CO   32
#define SP   9
#define NNZE 147456
#define KTOT (SP * CI)   // 576
#define ELLW 32          // padded entries per row (lambda=3; overflow P ~1e-21)

// half2 bit-cast helpers (defined BEFORE any use)
__device__ __forceinline__ __half2 u2h2(unsigned int u) {
    __half2 h;
    *reinterpret_cast<unsigned int*>(&h) = u;
    return h;
}
__device__ __forceinline__ unsigned int h22u(__half2 h) {
    return *reinterpret_cast<unsigned int*>(&h);
}

// ---------------------------------------------------------------------------
// Device scratch (statics zero-initialized; g_cnt re-zeroed by spiral_mma).
// NOTE: g_ellc entries beyond cnt may hold stale-but-valid cols from the
// previous call (or zeros on first call); they are only ever multiplied by 0.
// ---------------------------------------------------------------------------
__device__ int   g_cnt[NU];
__device__ __align__(16) int   g_ellc[NU * ELLW];     // col per slot
__device__ __align__(16) float g_ellv[NU * ELLW];     // val per slot
// x converted to fp16: [b][col][64ch]
__device__ __align__(256) unsigned short g_xh[(size_t)BB * ND * CI];
// pooled: per row a 1KB chunk: b0..b7 x 128B (fp16, 64 ch);
// within batch b: 16B unit u stored at offset ((u ^ b) << 4)
__device__ __align__(256) unsigned char g_pool[(size_t)NU * 1024];
// weight fp16, [s][n=32][k=64] with 16B-unit XOR swizzle, ldmatrix-ready
__device__ __align__(256) unsigned short g_wh[SP * CO * CI];

// ---------------------------------------------------------------------------
// Launch 0: ELL build + weight fp16/swizzle prepack + x -> fp16 conversion
// ---------------------------------------------------------------------------
__global__ void ell_fill(const int*   __restrict__ rows,
                         const int*   __restrict__ cols,
                         const float* __restrict__ vals,
                         const float* __restrict__ weight,
                         const float* __restrict__ x) {
    int i = blockIdx.x * blockDim.x + threadIdx.x;
    if (i < NNZE) {
        int row = __ldg(rows + i);
        int p = atomicAdd(&g_cnt[row], 1);
        if (p < ELLW) {
            g_ellc[row * ELLW + p] = __ldg(cols + i);
            g_ellv[row * ELLW + p] = __ldg(vals + i);
        }
    }
    if (i < SP * CO * CI) {
        int k = i & 63;
        int n = (i >> 6) & 31;
        int s = i >> 11;
        float v = __ldg(weight + n * KTOT + s * CI + k);
        int unit = k >> 3;
        int within = (k * 2) & 15;
        int byte = s * 4096 + n * 128 + ((unit ^ (n & 7)) << 4) + within;
        g_wh[byte >> 1] = __half_as_ushort(__float2half_rn(v));
    }
    // x -> fp16, 8 floats per chunk, grid-stride
    const int total = NNZE;           // grid*block
    uint4* dst = reinterpret_cast<uint4*>(g_xh);
    for (int j = i; j < (BB * ND * CI) / 8; j += total) {
        const float4* s = reinterpret_cast<const float4*>(x) + (size_t)j * 2;
        float4 a = __ldg(s), b = __ldg(s + 1);
        uint4 o;
        o.x = h22u(__floats2half2_rn(a.x, a.y));
        o.y = h22u(__floats2half2_rn(a.z, a.w));
        o.z = h22u(__floats2half2_rn(b.x, b.y));
        o.w = h22u(__floats2half2_rn(b.z, b.w));
        dst[j] = o;
    }
}

// ---------------------------------------------------------------------------
// Launch 1: gather-pool from ELL (fp16 x) -> per-row 1KB fp16 chunks.
// thread = (row, c4). First 4 ELL descriptors loaded upfront as int4/float4
// (always-valid padded slots); 4 independent predicated bodies maximize MLP;
// scalar tail for cnt>4 (P ~18%).
// ---------------------------------------------------------------------------
__global__ void __launch_bounds__(256)
gather_pool() {
    int gt  = blockIdx.x * blockDim.x + threadIdx.x;
    int row = gt >> 4;
    int c4  = gt & 15;
    if (row >= NU) return;

    int cnt = g_cnt[row];
    if (cnt > ELLW) cnt = ELLW;

    float4 acc[BB];
#pragma unroll
    for (int b = 0; b < BB; b++) acc[b] = make_float4(0.f, 0.f, 0.f, 0.f);

    const int*   ec = g_ellc + row * ELLW;
    const float* ev = g_ellv + row * ELLW;

    // Head: up to 4 entries, descriptors prefetched, bodies independent.
    int4   c03 = *reinterpret_cast<const int4*>(ec);
    float4 v03 = *reinterpret_cast<const float4*>(ev);
    const int   hc[4] = {c03.x, c03.y, c03.z, c03.w};
    const float hv[4] = {v03.x, v03.y, v03.z, v03.w};
#pragma unroll
    for (int i = 0; i < 4; i++) {
        if (i < cnt) {
            float v = hv[i];
            const uint2* xp = reinterpret_cast<const uint2*>(g_xh)
                            + ((size_t)hc[i] * 16 + c4);
#pragma unroll
            for (int b = 0; b < BB; b++) {
                uint2 xv = __ldg(xp + (size_t)b * (ND * 16));
                float2 f0 = __half22float2(u2h2(xv.x));
                float2 f1 = __half22float2(u2h2(xv.y));
                acc[b].x += v * f0.x; acc[b].y += v * f0.y;
                acc[b].z += v * f1.x; acc[b].w += v * f1.y;
            }
        }
    }
    // Tail: rare (cnt>4)
    for (int i = 4; i < cnt; i++) {
        int   col = __ldg(ec + i);
        float v   = __ldg(ev + i);
        const uint2* xp = reinterpret_cast<const uint2*>(g_xh)
                        + ((size_t)col * 16 + c4);
#pragma unroll
        for (int b = 0; b < BB; b++) {
            uint2 xv = __ldg(xp + (size_t)b * (ND * 16));
            float2 f0 = __half22float2(u2h2(xv.x));
            float2 f1 = __half22float2(u2h2(xv.y));
            acc[b].x += v * f0.x; acc[b].y += v * f0.y;
            acc[b].z += v * f1.x; acc[b].w += v * f1.y;
        }
    }

    const int u = c4 >> 1;
    const int h = c4 & 1;
    unsigned char* chunk = g_pool + (size_t)row * 1024;
#pragma unroll
    for (int b = 0; b < BB; b++) {
        ushort4 hh;
        hh.x = __half_as_ushort(__float2half_rn(acc[b].x));
        hh.y = __half_as_ushort(__float2half_rn(acc[b].y));
        hh.z = __half_as_ushort(__float2half_rn(acc[b].z));
        hh.w = __half_as_ushort(__float2half_rn(acc[b].w));
        int off = b * 128 + ((u ^ b) << 4) + h * 8;
        *reinterpret_cast<ushort4*>(chunk + off) = hh;
    }
}

// ---------------------------------------------------------------------------
// Launch 2: fused spiral gather + mma.sync fp16 GEMM + bias + relu.
// Block = 12 spiral rows x 8 batches = 96 GEMM rows x 32 outs, 6 warps.
// smem ~33.8KB -> 6 CTAs/SM. Also re-zeros g_cnt for the next call.
// (unchanged from round 15: near its L2-gather bandwidth floor)
// ---------------------------------------------------------------------------
#define TROWS   12
#define ASLOT   (TROWS * 1024)              // 12288
#define WSLOT   4096
#define NTHR    (TROWS * 16)                // 192 threads, 6 warps
#define SM_MBAR 0
#define SM_SG   64                          // 108 ints
#define SM_A    1024
#define SM_W    (SM_A + 2 * ASLOT)          // 25600
#define SM_TOT  (SM_W + 2 * WSLOT)          // 33792 B

__device__ __forceinline__ uint32_t smem_u32(const void* p) {
    uint32_t a;
    asm("{ .reg .u64 t; cvta.to.shared.u64 t, %1; cvt.u32.u64 %0, t; }" : "=r"(a) : "l"(p));
    return a;
}
__device__ __forceinline__ void mbar_init(uint32_t m, uint32_t cnt) {
    asm volatile("mbarrier.init.shared.b64 [%0], %1;" :: "r"(m), "r"(cnt) : "memory");
}
__device__ __forceinline__ void mbar_expect_tx(uint32_t m, uint32_t bytes) {
    asm volatile("mbarrier.arrive.expect_tx.shared.b64 _, [%0], %1;"
                 :: "r"(m), "r"(bytes) : "memory");
}
__device__ __forceinline__ void mbar_wait(uint32_t m, uint32_t parity) {
    asm volatile(
        "{\n\t.reg .pred P;\n"
        "W_%=:\n\t"
        "mbarrier.try_wait.parity.shared::cta.b64 P, [%0], %1;\n\t"
        "@!P bra W_%=;\n\t}"
        :: "r"(m), "r"(parity) : "memory");
}
__device__ __forceinline__ void bulk_g2s(uint32_t dst, const void* src,
                                         uint32_t bytes, uint32_t mbar) {
    asm volatile(
        "cp.async.bulk.shared::cluster.global.mbarrier::complete_tx::bytes "
        "[%0], [%1], %2, [%3];"
        :: "r"(dst), "l"(src), "r"(bytes), "r"(mbar) : "memory");
}
__device__ __forceinline__ void ldsm4(uint32_t addr, uint32_t& r0, uint32_t& r1,
                                      uint32_t& r2, uint32_t& r3) {
    asm volatile("ldmatrix.sync.aligned.m8n8.x4.shared.b16 {%0,%1,%2,%3}, [%4];"
                 : "=r"(r0), "=r"(r1), "=r"(r2), "=r"(r3) : "r"(addr));
}
__device__ __forceinline__ void mma_f16(float* c, uint32_t a0, uint32_t a1,
                                        uint32_t a2, uint32_t a3,
                                        uint32_t b0, uint32_t b1) {
    asm volatile(
        "mma.sync.aligned.m16n8k16.row.col.f32.f16.f16.f32 "
        "{%0,%1,%2,%3}, {%4,%5,%6,%7}, {%8,%9}, {%0,%1,%2,%3};"
        : "+f"(c[0]), "+f"(c[1]), "+f"(c[2]), "+f"(c[3])
        : "r"(a0), "r"(a1), "r"(a2), "r"(a3), "r"(b0), "r"(b1));
}

__global__ void __launch_bounds__(NTHR, 6)
spiral_mma(const int*   __restrict__ sidx,
           const float* __restrict__ bias,
           float*       __restrict__ out) {
    extern __shared__ char smraw[];
    uint32_t smb = smem_u32(smraw);

    const int tid  = threadIdx.x;
    const int wid  = tid >> 5;
    const int lane = tid & 31;
    const int n0   = blockIdx.x * TROWS;

    // Re-zero g_cnt for the next call (4096 blocks x 192 covers NU)
    {
        int i = blockIdx.x * NTHR + tid;
        if (i < NU) g_cnt[i] = 0;
    }

    int* Sg = reinterpret_cast<int*>(smraw + SM_SG);

    if (tid == 0) {
        mbar_init(smb + SM_MBAR + 0, 1);
        mbar_init(smb + SM_MBAR + 8, 1);
    }
    if (tid < TROWS * SP) Sg[tid] = __ldg(sidx + (size_t)n0 * SP + tid);
    __syncthreads();

    auto gather = [&](int s) {
        int slot = s & 1;
        uint32_t mbar = smb + SM_MBAR + slot * 8;
        if (tid == 0) mbar_expect_tx(mbar, ASLOT + WSLOT);
        if (tid < TROWS) {
            int idx = Sg[tid * SP + s];
            bulk_g2s(smb + SM_A + slot * ASLOT + tid * 1024,
                     g_pool + (size_t)idx * 1024, 1024, mbar);
        } else if (tid == TROWS) {
            bulk_g2s(smb + SM_W + slot * WSLOT,
                     reinterpret_cast<const char*>(g_wh) + s * 4096, 4096, mbar);
        }
    };

    gather(0);
    gather(1);

    float acc[4][4];
#pragma unroll
    for (int i = 0; i < 4; i++)
#pragma unroll
        for (int j = 0; j < 4; j++) acc[i][j] = 0.f;

    const int m8 = lane >> 3;
    const int t8 = lane & 7;
    const int rl = 2 * wid + (m8 & 1);     // local spiral row 0..11
    const int mk = m8 >> 1;

#pragma unroll 1
    for (int s = 0; s < SP; s++) {
        int slot = s & 1;
        mbar_wait(smb + SM_MBAR + slot * 8, (s >> 1) & 1);

        uint32_t abase = smb + SM_A + slot * ASLOT;
        uint32_t wbase = smb + SM_W + slot * WSLOT;

#pragma unroll
        for (int ks = 0; ks < 4; ks++) {
            int unit = 2 * ks + mk;
            uint32_t aaddr = abase + rl * 1024 + t8 * 128 + ((unit ^ t8) << 4);
            uint32_t ah[4];
            ldsm4(aaddr, ah[0], ah[1], ah[2], ah[3]);
            uint32_t bh0[4], bh1[4];
#pragma unroll
            for (int nb = 0; nb < 2; nb++) {
                int nrow = nb * 16 + (m8 & 1) * 8 + t8;
                uint32_t baddr = wbase + nrow * 128 + ((unit ^ (nrow & 7)) << 4);
                uint32_t* bh = nb ? bh1 : bh0;
                ldsm4(baddr, bh[0], bh[1], bh[2], bh[3]);
            }
            mma_f16(acc[0], ah[0], ah[1], ah[2], ah[3], bh0[0], bh0[2]);
            mma_f16(acc[1], ah[0], ah[1], ah[2], ah[3], bh0[1], bh0[3]);
            mma_f16(acc[2], ah[0], ah[1], ah[2], ah[3], bh1[0], bh1[2]);
            mma_f16(acc[3], ah[0], ah[1], ah[2], ah[3], bh1[1], bh1[3]);
        }

        __syncthreads();
        if (s + 2 < SP) gather(s + 2);
    }

    // Epilogue: GEMM row g = wid*16 + (lane>>2) (+8): rl = g>>3, batch = g&7
    const int gr  = wid * 16 + (lane >> 2);
    const int col = (lane & 3) * 2;
    const int b0r = gr & 7;
    const int nr0 = n0 + (gr >> 3);
    const int nr1 = n0 + ((gr + 8) >> 3);
    float* po0 = out + ((size_t)b0r * NU + nr0) * CO;
    float* po1 = out + ((size_t)b0r * NU + nr1) * CO;
#pragma unroll
    for (int nt = 0; nt < 4; nt++) {
        int o = nt * 8 + col;
        float c0 = __ldg(bias + o), c1 = __ldg(bias + o + 1);
        float2 v0 = make_float2(fmaxf(acc[nt][0] + c0, 0.f), fmaxf(acc[nt][1] + c1, 0.f));
        float2 v1 = make_float2(fmaxf(acc[nt][2] + c0, 0.f), fmaxf(acc[nt][3] + c1, 0.f));
        *reinterpret_cast<float2*>(po0 + o) = v0;
        *reinterpret_cast<float2*>(po1 + o) = v1;
    }
}

// ---------------------------------------------------------------------------
// Launch (3 kernels)
// ---------------------------------------------------------------------------
extern "C" void kernel_launch(void* const* d_in, const int* in_sizes, int n_in,
                              void* d_out, int out_size) {
    const float* x        = (const float*)d_in[0];
    const int*   up_rows  = (const int*)  d_in[1];
    const int*   up_cols  = (const int*)  d_in[2];
    const float* up_vals  = (const float*)d_in[3];
    const int*   sidx     = (const int*)  d_in[4];
    const float* weight   = (const float*)d_in[5];
    const float* bias     = (const float*)d_in[6];
    float*       out      = (float*)d_out;

    ell_fill<<<(NNZE + 255) / 256, 256>>>(up_rows, up_cols, up_vals, weight, x);
    gather_pool<<<(NU * 16) / 256, 256>>>();

    cudaFuncSetAttribute(spiral_mma,
                         cudaFuncAttributeMaxDynamicSharedMemorySize, SM_TOT);
    spiral_mma<<<NU / TROWS, NTHR, SM_TOT>>>(sidx, bias, out);
}

// round 17
// speedup vs baseline: 6.3334x; 1.0257x over previous
#include <cuda_runtime.h>
#include <cuda_fp16.h>
#include <cstdint>

// Problem constants
#define BB   8
#define ND   12288
#define NU   49152
#define CI   64
#define CO   32
#define SP   9
#define NNZE 147456
#define KTOT (SP * CI)   // 576
#define ELLW 32          // padded entries per row (lambda=3; overflow P ~1e-21)

// half2 bit-cast helpers (defined BEFORE any use)
__device__ __forceinline__ __half2 u2h2(unsigned int u) {
    __half2 h;
    *reinterpret_cast<unsigned int*>(&h) = u;
    return h;
}
__device__ __forceinline__ unsigned int h22u(__half2 h) {
    return *reinterpret_cast<unsigned int*>(&h);
}

// ---------------------------------------------------------------------------
// Device scratch (statics zero-initialized; g_cnt re-zeroed by spiral_mma).
// g_ellc slots beyond cnt may hold stale-but-valid cols; only multiplied by 0.
// ---------------------------------------------------------------------------
__device__ int   g_cnt[NU];
__device__ __align__(16) int   g_ellc[NU * ELLW];     // col per slot
__device__ __align__(16) float g_ellv[NU * ELLW];     // val per slot
// x converted to fp16: [b][col][64ch]
__device__ __align__(256) unsigned short g_xh[(size_t)BB * ND * CI];
// pooled: per row a 1KB chunk: b0..b7 x 128B (fp16, 64 ch);
// within batch b: 16B unit u stored at offset ((u ^ b) << 4)
__device__ __align__(256) unsigned char g_pool[(size_t)NU * 1024];
// weight fp16, [s][n=32][k=64] with 16B-unit XOR swizzle, ldmatrix-ready
__device__ __align__(256) unsigned short g_wh[SP * CO * CI];

// ---------------------------------------------------------------------------
// Launch 0: ELL build + weight fp16/swizzle prepack + x -> fp16 conversion
// ---------------------------------------------------------------------------
__global__ void ell_fill(const int*   __restrict__ rows,
                         const int*   __restrict__ cols,
                         const float* __restrict__ vals,
                         const float* __restrict__ weight,
                         const float* __restrict__ x) {
    int i = blockIdx.x * blockDim.x + threadIdx.x;
    if (i < NNZE) {
        int row = __ldg(rows + i);
        int p = atomicAdd(&g_cnt[row], 1);
        if (p < ELLW) {
            g_ellc[row * ELLW + p] = __ldg(cols + i);
            g_ellv[row * ELLW + p] = __ldg(vals + i);
        }
    }
    if (i < SP * CO * CI) {
        int k = i & 63;
        int n = (i >> 6) & 31;
        int s = i >> 11;
        float v = __ldg(weight + n * KTOT + s * CI + k);
        int unit = k >> 3;
        int within = (k * 2) & 15;
        int byte = s * 4096 + n * 128 + ((unit ^ (n & 7)) << 4) + within;
        g_wh[byte >> 1] = __half_as_ushort(__float2half_rn(v));
    }
    // x -> fp16, 8 floats per chunk, grid-stride
    const int total = NNZE;           // grid*block
    uint4* dst = reinterpret_cast<uint4*>(g_xh);
    for (int j = i; j < (BB * ND * CI) / 8; j += total) {
        const float4* s = reinterpret_cast<const float4*>(x) + (size_t)j * 2;
        float4 a = __ldg(s), b = __ldg(s + 1);
        uint4 o;
        o.x = h22u(__floats2half2_rn(a.x, a.y));
        o.y = h22u(__floats2half2_rn(a.z, a.w));
        o.z = h22u(__floats2half2_rn(b.x, b.y));
        o.w = h22u(__floats2half2_rn(b.z, b.w));
        dst[j] = o;
    }
}

// ---------------------------------------------------------------------------
// Launch 1: gather-pool from ELL (fp16 x) -> per-row 1KB fp16 chunks.
// thread = (row, c4, batch-half): 32 threads/row, each owns 4 batches.
// Halved accumulator state (~45 regs) + 2x warps -> deep MLP latency hiding.
// ---------------------------------------------------------------------------
__global__ void __launch_bounds__(256)
gather_pool() {
    int gt  = blockIdx.x * blockDim.x + threadIdx.x;
    int row = gt >> 5;
    int sub = gt & 31;
    int c4  = sub & 15;         // 8B unit-half within 128B row
    int bh  = sub >> 4;         // batch group: batches bh*4 .. bh*4+3
    if (row >= NU) return;

    int cnt = g_cnt[row];
    if (cnt > ELLW) cnt = ELLW;

    float4 acc[4];
#pragma unroll
    for (int b = 0; b < 4; b++) acc[b] = make_float4(0.f, 0.f, 0.f, 0.f);

    const int*   ec = g_ellc + row * ELLW;
    const float* ev = g_ellv + row * ELLW;
    const size_t bbase = (size_t)(bh * 4) * (ND * 16);   // uint2 units

    // Head: up to 4 entries, descriptors prefetched, bodies independent.
    int4   c03 = *reinterpret_cast<const int4*>(ec);
    float4 v03 = *reinterpret_cast<const float4*>(ev);
    const int   hc[4] = {c03.x, c03.y, c03.z, c03.w};
    const float hv[4] = {v03.x, v03.y, v03.z, v03.w};
#pragma unroll
    for (int i = 0; i < 4; i++) {
        if (i < cnt) {
            float v = hv[i];
            const uint2* xp = reinterpret_cast<const uint2*>(g_xh)
                            + bbase + ((size_t)hc[i] * 16 + c4);
#pragma unroll
            for (int b = 0; b < 4; b++) {
                uint2 xv = __ldg(xp + (size_t)b * (ND * 16));
                float2 f0 = __half22float2(u2h2(xv.x));
                float2 f1 = __half22float2(u2h2(xv.y));
                acc[b].x += v * f0.x; acc[b].y += v * f0.y;
                acc[b].z += v * f1.x; acc[b].w += v * f1.y;
            }
        }
    }
    // Tail: rare (cnt>4)
    for (int i = 4; i < cnt; i++) {
        int   col = __ldg(ec + i);
        float v   = __ldg(ev + i);
        const uint2* xp = reinterpret_cast<const uint2*>(g_xh)
                        + bbase + ((size_t)col * 16 + c4);
#pragma unroll
        for (int b = 0; b < 4; b++) {
            uint2 xv = __ldg(xp + (size_t)b * (ND * 16));
            float2 f0 = __half22float2(u2h2(xv.x));
            float2 f1 = __half22float2(u2h2(xv.y));
            acc[b].x += v * f0.x; acc[b].y += v * f0.y;
            acc[b].z += v * f1.x; acc[b].w += v * f1.y;
        }
    }

    const int u = c4 >> 1;
    const int h = c4 & 1;
    unsigned char* chunk = g_pool + (size_t)row * 1024;
#pragma unroll
    for (int b = 0; b < 4; b++) {
        int bb = bh * 4 + b;
        ushort4 hh;
        hh.x = __half_as_ushort(__float2half_rn(acc[b].x));
        hh.y = __half_as_ushort(__float2half_rn(acc[b].y));
        hh.z = __half_as_ushort(__float2half_rn(acc[b].z));
        hh.w = __half_as_ushort(__float2half_rn(acc[b].w));
        int off = bb * 128 + ((u ^ bb) << 4) + h * 8;
        *reinterpret_cast<ushort4*>(chunk + off) = hh;
    }
}

// ---------------------------------------------------------------------------
// Launch 2: fused spiral gather + mma.sync fp16 GEMM + bias + relu.
// Block = 12 spiral rows x 8 batches = 96 GEMM rows x 32 outs, 6 warps.
// smem ~33.8KB -> 6 CTAs/SM. Also re-zeros g_cnt for the next call.
// (unchanged: near its L2-gather bandwidth floor)
// ---------------------------------------------------------------------------
#define TROWS   12
#define ASLOT   (TROWS * 1024)              // 12288
#define WSLOT   4096
#define NTHR    (TROWS * 16)                // 192 threads, 6 warps
#define SM_MBAR 0
#define SM_SG   64                          // 108 ints
#define SM_A    1024
#define SM_W    (SM_A + 2 * ASLOT)          // 25600
#define SM_TOT  (SM_W + 2 * WSLOT)          // 33792 B

__device__ __forceinline__ uint32_t smem_u32(const void* p) {
    uint32_t a;
    asm("{ .reg .u64 t; cvta.to.shared.u64 t, %1; cvt.u32.u64 %0, t; }" : "=r"(a) : "l"(p));
    return a;
}
__device__ __forceinline__ void mbar_init(uint32_t m, uint32_t cnt) {
    asm volatile("mbarrier.init.shared.b64 [%0], %1;" :: "r"(m), "r"(cnt) : "memory");
}
__device__ __forceinline__ void mbar_expect_tx(uint32_t m, uint32_t bytes) {
    asm volatile("mbarrier.arrive.expect_tx.shared.b64 _, [%0], %1;"
                 :: "r"(m), "r"(bytes) : "memory");
}
__device__ __forceinline__ void mbar_wait(uint32_t m, uint32_t parity) {
    asm volatile(
        "{\n\t.reg .pred P;\n"
        "W_%=:\n\t"
        "mbarrier.try_wait.parity.shared::cta.b64 P, [%0], %1;\n\t"
        "@!P bra W_%=;\n\t}"
        :: "r"(m), "r"(parity) : "memory");
}
__device__ __forceinline__ void bulk_g2s(uint32_t dst, const void* src,
                                         uint32_t bytes, uint32_t mbar) {
    asm volatile(
        "cp.async.bulk.shared::cluster.global.mbarrier::complete_tx::bytes "
        "[%0], [%1], %2, [%3];"
        :: "r"(dst), "l"(src), "r"(bytes), "r"(mbar) : "memory");
}
__device__ __forceinline__ void ldsm4(uint32_t addr, uint32_t& r0, uint32_t& r1,
                                      uint32_t& r2, uint32_t& r3) {
    asm volatile("ldmatrix.sync.aligned.m8n8.x4.shared.b16 {%0,%1,%2,%3}, [%4];"
                 : "=r"(r0), "=r"(r1), "=r"(r2), "=r"(r3) : "r"(addr));
}
__device__ __forceinline__ void mma_f16(float* c, uint32_t a0, uint32_t a1,
                                        uint32_t a2, uint32_t a3,
                                        uint32_t b0, uint32_t b1) {
    asm volatile(
        "mma.sync.aligned.m16n8k16.row.col.f32.f16.f16.f32 "
        "{%0,%1,%2,%3}, {%4,%5,%6,%7}, {%8,%9}, {%0,%1,%2,%3};"
        : "+f"(c[0]), "+f"(c[1]), "+f"(c[2]), "+f"(c[3])
        : "r"(a0), "r"(a1), "r"(a2), "r"(a3), "r"(b0), "r"(b1));
}

__global__ void __launch_bounds__(NTHR, 6)
spiral_mma(const int*   __restrict__ sidx,
           const float* __restrict__ bias,
           float*       __restrict__ out) {
    extern __shared__ char smraw[];
    uint32_t smb = smem_u32(smraw);

    const int tid  = threadIdx.x;
    const int wid  = tid >> 5;
    const int lane = tid & 31;
    const int n0   = blockIdx.x * TROWS;

    // Re-zero g_cnt for the next call (4096 blocks x 192 covers NU)
    {
        int i = blockIdx.x * NTHR + tid;
        if (i < NU) g_cnt[i] = 0;
    }

    int* Sg = reinterpret_cast<int*>(smraw + SM_SG);

    if (tid == 0) {
        mbar_init(smb + SM_MBAR + 0, 1);
        mbar_init(smb + SM_MBAR + 8, 1);
    }
    if (tid < TROWS * SP) Sg[tid] = __ldg(sidx + (size_t)n0 * SP + tid);
    __syncthreads();

    auto gather = [&](int s) {
        int slot = s & 1;
        uint32_t mbar = smb + SM_MBAR + slot * 8;
        if (tid == 0) mbar_expect_tx(mbar, ASLOT + WSLOT);
        if (tid < TROWS) {
            int idx = Sg[tid * SP + s];
            bulk_g2s(smb + SM_A + slot * ASLOT + tid * 1024,
                     g_pool + (size_t)idx * 1024, 1024, mbar);
        } else if (tid == TROWS) {
            bulk_g2s(smb + SM_W + slot * WSLOT,
                     reinterpret_cast<const char*>(g_wh) + s * 4096, 4096, mbar);
        }
    };

    gather(0);
    gather(1);

    float acc[4][4];
#pragma unroll
    for (int i = 0; i < 4; i++)
#pragma unroll
        for (int j = 0; j < 4; j++) acc[i][j] = 0.f;

    const int m8 = lane >> 3;
    const int t8 = lane & 7;
    const int rl = 2 * wid + (m8 & 1);     // local spiral row 0..11
    const int mk = m8 >> 1;

#pragma unroll 1
    for (int s = 0; s < SP; s++) {
        int slot = s & 1;
        mbar_wait(smb + SM_MBAR + slot * 8, (s >> 1) & 1);

        uint32_t abase = smb + SM_A + slot * ASLOT;
        uint32_t wbase = smb + SM_W + slot * WSLOT;

#pragma unroll
        for (int ks = 0; ks < 4; ks++) {
            int unit = 2 * ks + mk;
            uint32_t aaddr = abase + rl * 1024 + t8 * 128 + ((unit ^ t8) << 4);
            uint32_t ah[4];
            ldsm4(aaddr, ah[0], ah[1], ah[2], ah[3]);
            uint32_t bh0[4], bh1[4];
#pragma unroll
            for (int nb = 0; nb < 2; nb++) {
                int nrow = nb * 16 + (m8 & 1) * 8 + t8;
                uint32_t baddr = wbase + nrow * 128 + ((unit ^ (nrow & 7)) << 4);
                uint32_t* bh = nb ? bh1 : bh0;
                ldsm4(baddr, bh[0], bh[1], bh[2], bh[3]);
            }
            mma_f16(acc[0], ah[0], ah[1], ah[2], ah[3], bh0[0], bh0[2]);
            mma_f16(acc[1], ah[0], ah[1], ah[2], ah[3], bh0[1], bh0[3]);
            mma_f16(acc[2], ah[0], ah[1], ah[2], ah[3], bh1[0], bh1[2]);
            mma_f16(acc[3], ah[0], ah[1], ah[2], ah[3], bh1[1], bh1[3]);
        }

        __syncthreads();
        if (s + 2 < SP) gather(s + 2);
    }

    // Epilogue: GEMM row g = wid*16 + (lane>>2) (+8): rl = g>>3, batch = g&7
    const int gr  = wid * 16 + (lane >> 2);
    const int col = (lane & 3) * 2;
    const int b0r = gr & 7;
    const int nr0 = n0 + (gr >> 3);
    const int nr1 = n0 + ((gr + 8) >> 3);
    float* po0 = out + ((size_t)b0r * NU + nr0) * CO;
    float* po1 = out + ((size_t)b0r * NU + nr1) * CO;
#pragma unroll
    for (int nt = 0; nt < 4; nt++) {
        int o = nt * 8 + col;
        float c0 = __ldg(bias + o), c1 = __ldg(bias + o + 1);
        float2 v0 = make_float2(fmaxf(acc[nt][0] + c0, 0.f), fmaxf(acc[nt][1] + c1, 0.f));
        float2 v1 = make_float2(fmaxf(acc[nt][2] + c0, 0.f), fmaxf(acc[nt][3] + c1, 0.f));
        *reinterpret_cast<float2*>(po0 + o) = v0;
        *reinterpret_cast<float2*>(po1 + o) = v1;
    }
}

// ---------------------------------------------------------------------------
// Launch (3 kernels)
// ---------------------------------------------------------------------------
extern "C" void kernel_launch(void* const* d_in, const int* in_sizes, int n_in,
                              void* d_out, int out_size) {
    const float* x        = (const float*)d_in[0];
    const int*   up_rows  = (const int*)  d_in[1];
    const int*   up_cols  = (const int*)  d_in[2];
    const float* up_vals  = (const float*)d_in[3];
    const int*   sidx     = (const int*)  d_in[4];
    const float* weight   = (const float*)d_in[5];
    const float* bias     = (const float*)d_in[6];
    float*       out      = (float*)d_out;

    ell_fill<<<(NNZE + 255) / 256, 256>>>(up_rows, up_cols, up_vals, weight, x);
    gather_pool<<<(NU * 32 + 255) / 256, 256>>>();

    cudaFuncSetAttribute(spiral_mma,
                         cudaFuncAttributeMaxDynamicSharedMemorySize, SM_TOT);
    spiral_mma<<<NU / TROWS, NTHR, SM_TOT>>>(sidx, bias, out);
}